// round 4
// baseline (speedup 1.0000x reference)
#include <cuda_runtime.h>
#include <cuda_bf16.h>
#include <math.h>

// Problem constants
#define NN    8192
#define HH    512
#define DD    256
#define GG    64
#define M2    16384          // 2*N rows through the MLP
#define INV_TAU 2.0f
#define EPS_G 1e-6f
#define EPS_L 1e-5f

// ---------------- scratch (static device allocations; no cudaMalloc) ----------------
__device__ float g_h1[M2 * HH];          // 32 MB
__device__ float g_h2[M2 * HH];          // 32 MB
__device__ float g_proj[NN * (2 * DD)];  // aligned mirror of d_out[1..]  (16 MB)
__device__ float g_inv_na[NN];
__device__ float g_inv_nb[NN];
__device__ float g_rowsum[NN];
__device__ float g_colsum[NN];
__device__ float g_rowdot[NN];
__device__ float g_coldot[NN];
__device__ float g_bsim[GG * GG];
__device__ float g_psg[GG];

// ---------------- zero accumulators ----------------
__global__ void zero_kernel() {
    int t = blockIdx.x * blockDim.x + threadIdx.x;
    if (t < NN) {
        g_rowsum[t] = 0.f; g_colsum[t] = 0.f;
        g_rowdot[t] = 0.f; g_coldot[t] = 0.f;
    }
    if (t < GG * GG) g_bsim[t] = 0.f;
    if (t < GG)      g_psg[t]  = 0.f;
}

// ---------------- generic 128x128x(8x8) SGEMM with fused epilogue ----------------
// C[M,N] = A[M,K] @ W[K,N] (+bias), then mode 0: DyT tanh(a*h)*g+be ; mode 1: SiLU
#define BM 128
#define BN 128
#define BKC 16

__global__ __launch_bounds__(256) void sgemm_ep(
    const float* __restrict__ A, int lda,
    const float* __restrict__ W, int ldw,
    const float* __restrict__ bias,
    const float* __restrict__ aP, const float* __restrict__ gP, const float* __restrict__ beP,
    float* __restrict__ C, int ldc,
    float* __restrict__ C2,           // optional second (unaligned ok) output, same indexing
    int K, int mode)
{
    __shared__ float As[BKC][BM + 4];
    __shared__ float Bs[BKC][BN + 4];
    int tid = threadIdx.x;
    int tx = tid & 15, ty = tid >> 4;
    int row0 = blockIdx.y * BM, col0 = blockIdx.x * BN;

    float acc[8][8];
#pragma unroll
    for (int i = 0; i < 8; i++)
#pragma unroll
        for (int j = 0; j < 8; j++) acc[i][j] = 0.f;

    for (int k0 = 0; k0 < K; k0 += BKC) {
        // load A tile (128 rows x 16 k), store transposed
#pragma unroll
        for (int l = 0; l < 2; l++) {
            int e = tid * 2 + l;          // 0..511
            int ar = e >> 2;              // row within tile
            int akq = e & 3;              // k-quad
            float4 v = *reinterpret_cast<const float4*>(
                &A[(size_t)(row0 + ar) * lda + k0 + akq * 4]);
            As[akq * 4 + 0][ar] = v.x;
            As[akq * 4 + 1][ar] = v.y;
            As[akq * 4 + 2][ar] = v.z;
            As[akq * 4 + 3][ar] = v.w;
        }
        // load W tile (16 k x 128 cols), direct
#pragma unroll
        for (int l = 0; l < 2; l++) {
            int e = tid * 2 + l;
            int bk = e >> 5;              // 0..15
            int bc = e & 31;              // col-quad
            *reinterpret_cast<float4*>(&Bs[bk][bc * 4]) =
                *reinterpret_cast<const float4*>(
                    &W[(size_t)(k0 + bk) * ldw + col0 + bc * 4]);
        }
        __syncthreads();
#pragma unroll
        for (int kk = 0; kk < BKC; kk++) {
            float ra[8], rb[8];
            float4 a0 = *reinterpret_cast<const float4*>(&As[kk][ty * 8]);
            float4 a1 = *reinterpret_cast<const float4*>(&As[kk][ty * 8 + 4]);
            float4 b0 = *reinterpret_cast<const float4*>(&Bs[kk][tx * 8]);
            float4 b1 = *reinterpret_cast<const float4*>(&Bs[kk][tx * 8 + 4]);
            ra[0] = a0.x; ra[1] = a0.y; ra[2] = a0.z; ra[3] = a0.w;
            ra[4] = a1.x; ra[5] = a1.y; ra[6] = a1.z; ra[7] = a1.w;
            rb[0] = b0.x; rb[1] = b0.y; rb[2] = b0.z; rb[3] = b0.w;
            rb[4] = b1.x; rb[5] = b1.y; rb[6] = b1.z; rb[7] = b1.w;
#pragma unroll
            for (int i = 0; i < 8; i++)
#pragma unroll
                for (int j = 0; j < 8; j++)
                    acc[i][j] = fmaf(ra[i], rb[j], acc[i][j]);
        }
        __syncthreads();
    }

    float a0 = (mode == 0) ? aP[0] : 0.f;
#pragma unroll
    for (int j = 0; j < 8; j++) {
        int c = col0 + tx * 8 + j;
        float bi = bias[c];
        float gg = (mode == 0) ? gP[c] : 0.f;
        float bb = (mode == 0) ? beP[c] : 0.f;
#pragma unroll
        for (int i = 0; i < 8; i++) {
            float v = acc[i][j] + bi;
            if (mode == 0) v = tanhf(a0 * v) * gg + bb;
            else           v = v / (1.f + expf(-v));
            size_t idx = (size_t)(row0 + ty * 8 + i) * ldc + c;
            C[idx] = v;
            if (C2) C2[idx] = v;
        }
    }
}

// ---------------- per-row inverse norms ----------------
__global__ void norm_kernel() {
    int warp = (blockIdx.x * blockDim.x + threadIdx.x) >> 5;
    int lane = threadIdx.x & 31;
    if (warp >= NN) return;
    const float* pa = g_proj + (size_t)warp * 512;
    float sa = 0.f, sb = 0.f;
#pragma unroll
    for (int k = lane; k < 256; k += 32) {
        float v = pa[k];        sa += v * v;
        float w = pa[256 + k];  sb += w * w;
    }
#pragma unroll
    for (int o = 16; o; o >>= 1) {
        sa += __shfl_xor_sync(0xffffffffu, sa, o);
        sb += __shfl_xor_sync(0xffffffffu, sb, o);
    }
    if (lane == 0) {
        g_inv_na[warp] = rsqrtf(sa);
        g_inv_nb[warp] = rsqrtf(sb);
    }
}

// ---------------- fused similarity tile: GEMM -> exp -> all reductions ----------------
__global__ __launch_bounds__(256) void sim_kernel(const float* __restrict__ pos,
                                                  const int* __restrict__ batch)
{
    __shared__ float As[BKC][BM + 4];
    __shared__ float Bs[BKC][BN + 4];
    __shared__ float s_rs[128], s_rd[128], s_cs[128], s_cd[128];
    __shared__ float s_ts;

    int tid = threadIdx.x;
    int tx = tid & 15, ty = tid >> 4;
    int i0 = blockIdx.y * 128, j0 = blockIdx.x * 128;

    if (tid < 128) { s_rs[tid] = 0.f; s_rd[tid] = 0.f; s_cs[tid] = 0.f; s_cd[tid] = 0.f; }
    if (tid == 0) s_ts = 0.f;

    float acc[8][8];
#pragma unroll
    for (int i = 0; i < 8; i++)
#pragma unroll
        for (int j = 0; j < 8; j++) acc[i][j] = 0.f;

    const float* Ap = g_proj;         // za_p rows, stride 512
    const float* Bp = g_proj + 256;   // zb_p rows, stride 512

    for (int k0 = 0; k0 < 256; k0 += BKC) {
#pragma unroll
        for (int l = 0; l < 2; l++) {
            int e = tid * 2 + l;
            int ar = e >> 2;
            int akq = e & 3;
            float4 v = *reinterpret_cast<const float4*>(
                &Ap[(size_t)(i0 + ar) * 512 + k0 + akq * 4]);
            As[akq * 4 + 0][ar] = v.x;
            As[akq * 4 + 1][ar] = v.y;
            As[akq * 4 + 2][ar] = v.z;
            As[akq * 4 + 3][ar] = v.w;
            float4 w = *reinterpret_cast<const float4*>(
                &Bp[(size_t)(j0 + ar) * 512 + k0 + akq * 4]);
            Bs[akq * 4 + 0][ar] = w.x;
            Bs[akq * 4 + 1][ar] = w.y;
            Bs[akq * 4 + 2][ar] = w.z;
            Bs[akq * 4 + 3][ar] = w.w;
        }
        __syncthreads();
#pragma unroll
        for (int kk = 0; kk < BKC; kk++) {
            float ra[8], rb[8];
            float4 a0 = *reinterpret_cast<const float4*>(&As[kk][ty * 8]);
            float4 a1 = *reinterpret_cast<const float4*>(&As[kk][ty * 8 + 4]);
            float4 b0 = *reinterpret_cast<const float4*>(&Bs[kk][tx * 8]);
            float4 b1 = *reinterpret_cast<const float4*>(&Bs[kk][tx * 8 + 4]);
            ra[0] = a0.x; ra[1] = a0.y; ra[2] = a0.z; ra[3] = a0.w;
            ra[4] = a1.x; ra[5] = a1.y; ra[6] = a1.z; ra[7] = a1.w;
            rb[0] = b0.x; rb[1] = b0.y; rb[2] = b0.z; rb[3] = b0.w;
            rb[4] = b1.x; rb[5] = b1.y; rb[6] = b1.z; rb[7] = b1.w;
#pragma unroll
            for (int i = 0; i < 8; i++)
#pragma unroll
                for (int j = 0; j < 8; j++)
                    acc[i][j] = fmaf(ra[i], rb[j], acc[i][j]);
        }
        __syncthreads();
    }

    // scale by inverse norms, exp
    float inva[8], invb[8];
#pragma unroll
    for (int i = 0; i < 8; i++) inva[i] = g_inv_na[i0 + ty * 8 + i];
#pragma unroll
    for (int j = 0; j < 8; j++) invb[j] = g_inv_nb[j0 + tx * 8 + j];
#pragma unroll
    for (int i = 0; i < 8; i++)
#pragma unroll
        for (int j = 0; j < 8; j++)
            acc[i][j] = expf(acc[i][j] * inva[i] * invb[j] * INV_TAU);

    // row reductions: rowsum + pos-weighted rowdot, tile sum
    float ts = 0.f;
#pragma unroll
    for (int i = 0; i < 8; i++) {
        int gi = i0 + ty * 8 + i;
        const float* pr = pos + (size_t)gi * NN + j0 + tx * 8;
        float4 p0 = *reinterpret_cast<const float4*>(pr);
        float4 p1 = *reinterpret_cast<const float4*>(pr + 4);
        float pv[8] = {p0.x, p0.y, p0.z, p0.w, p1.x, p1.y, p1.z, p1.w};
        float rsum = 0.f, rdot = 0.f;
#pragma unroll
        for (int j = 0; j < 8; j++) { rsum += acc[i][j]; rdot += acc[i][j] * pv[j]; }
        atomicAdd(&s_rs[ty * 8 + i], rsum);
        atomicAdd(&s_rd[ty * 8 + i], rdot);
        ts += rsum;
    }
    // col reductions: colsum + coldot[j] = sum_i m[i,j] * pos[j,i]
#pragma unroll
    for (int j = 0; j < 8; j++) {
        int gj = j0 + tx * 8 + j;
        const float* pc = pos + (size_t)gj * NN + i0 + ty * 8;
        float4 p0 = *reinterpret_cast<const float4*>(pc);
        float4 p1 = *reinterpret_cast<const float4*>(pc + 4);
        float pv[8] = {p0.x, p0.y, p0.z, p0.w, p1.x, p1.y, p1.z, p1.w};
        float csum = 0.f, cdot = 0.f;
#pragma unroll
        for (int i = 0; i < 8; i++) { csum += acc[i][j]; cdot += acc[i][j] * pv[i]; }
        atomicAdd(&s_cs[tx * 8 + j], csum);
        atomicAdd(&s_cd[tx * 8 + j], cdot);
    }
    // diagonal -> per-group positive-sim
    if (i0 == j0 && ty == tx) {
#pragma unroll
        for (int d = 0; d < 8; d++) {
            int gi = i0 + ty * 8 + d;
            atomicAdd(&g_psg[batch[gi]], acc[d][d]);
        }
    }
    atomicAdd(&s_ts, ts);
    __syncthreads();

    if (tid < 128) {
        atomicAdd(&g_rowsum[i0 + tid], s_rs[tid]);
        atomicAdd(&g_rowdot[i0 + tid], s_rd[tid]);
        atomicAdd(&g_colsum[j0 + tid], s_cs[tid]);
        atomicAdd(&g_coldot[j0 + tid], s_cd[tid]);
    }
    if (tid == 0) {
        atomicAdd(&g_bsim[batch[i0] * GG + batch[j0]], s_ts);
    }
}

// ---------------- final scalar loss ----------------
__global__ void finalize_kernel(float* __restrict__ out) {
    __shared__ float red[512];
    int t = threadIdx.x;

    float la = 0.f, lb = 0.f;
    for (int i = t; i < NN; i += 512) {
        la += logf(g_rowdot[i] / (g_rowsum[i] + EPS_G));
        lb += logf(g_coldot[i] / (g_colsum[i] + EPS_G));
    }
    red[t] = la; __syncthreads();
    for (int s = 256; s >= 1; s >>= 1) { if (t < s) red[t] += red[t + s]; __syncthreads(); }
    float suma = red[0]; __syncthreads();
    red[t] = lb; __syncthreads();
    for (int s = 256; s >= 1; s >>= 1) { if (t < s) red[t] += red[t + s]; __syncthreads(); }
    float sumb = red[0]; __syncthreads();

    float t0 = 0.f, t1 = 0.f, tin = 0.f;
    if (t < GG) {
        float graph = g_bsim[t * GG + t];
        float n0 = 0.f, n1 = 0.f;
        for (int a = 0; a < GG; a++) { n0 += g_bsim[a * GG + t]; n1 += g_bsim[t * GG + a]; }
        n0 -= graph; n1 -= graph;
        float psg = g_psg[t];
        t0  = logf(psg / (n0 + EPS_L));
        t1  = logf(psg / (n1 + EPS_L));
        tin = logf(psg / (graph - psg + EPS_L));
    }
    red[t] = t0; __syncthreads();
    for (int s = 256; s >= 1; s >>= 1) { if (t < s) red[t] += red[t + s]; __syncthreads(); }
    float s0 = red[0]; __syncthreads();
    red[t] = t1; __syncthreads();
    for (int s = 256; s >= 1; s >>= 1) { if (t < s) red[t] += red[t + s]; __syncthreads(); }
    float s1 = red[0]; __syncthreads();
    red[t] = tin; __syncthreads();
    for (int s = 256; s >= 1; s >>= 1) { if (t < s) red[t] += red[t + s]; __syncthreads(); }
    float sin_ = red[0]; __syncthreads();

    if (t == 0) {
        float lori_a = -suma / (float)NN;
        float lori_b = -sumb / (float)NN;
        float global_loss = 0.5f * lori_a + 0.5f * lori_b;
        float loss0 = s0 / (float)GG;
        float loss1 = s1 / (float)GG;
        float inter = 0.5f * (loss0 + loss1);
        float inner = -(sin_ / (float)GG);
        out[0] = global_loss + inter + inner;
    }
}

// ---------------- launcher ----------------
extern "C" void kernel_launch(void* const* d_in, const int* in_sizes, int n_in,
                              void* d_out, int out_size) {
    const float* za  = (const float*)d_in[0];
    const float* zb  = (const float*)d_in[1];
    const float* pos = (const float*)d_in[2];
    const int*   bat = (const int*)  d_in[3];
    const float* W1  = (const float*)d_in[4];
    const float* b1  = (const float*)d_in[5];
    const float* a1  = (const float*)d_in[6];
    const float* g1  = (const float*)d_in[7];
    const float* be1 = (const float*)d_in[8];
    const float* W2  = (const float*)d_in[9];
    const float* b2  = (const float*)d_in[10];
    const float* a2  = (const float*)d_in[11];
    const float* g2  = (const float*)d_in[12];
    const float* be2 = (const float*)d_in[13];
    const float* W3  = (const float*)d_in[14];
    const float* b3  = (const float*)d_in[15];
    float* out = (float*)d_out;

    float *h1p, *h2p, *projp;
    cudaGetSymbolAddress((void**)&h1p,   g_h1);
    cudaGetSymbolAddress((void**)&h2p,   g_h2);
    cudaGetSymbolAddress((void**)&projp, g_proj);

    zero_kernel<<<32, 256>>>();

    // layer 1: za rows -> h1[0..N), zb rows -> h1[N..2N)   (DyT epilogue)
    sgemm_ep<<<dim3(HH / BN, NN / BM), 256>>>(za, HH, W1, HH, b1, a1, g1, be1,
                                              h1p, HH, nullptr, HH, 0);
    sgemm_ep<<<dim3(HH / BN, NN / BM), 256>>>(zb, HH, W1, HH, b1, a1, g1, be1,
                                              h1p + (size_t)NN * HH, HH, nullptr, HH, 0);
    // layer 2: all 16384 rows in one launch (DyT epilogue)
    sgemm_ep<<<dim3(HH / BN, M2 / BM), 256>>>(h1p, HH, W2, HH, b2, a2, g2, be2,
                                              h2p, HH, nullptr, HH, 0);
    // layer 3: SiLU epilogue, interleaved [N, 512] into aligned scratch AND d_out+1
    sgemm_ep<<<dim3(DD / BN, NN / BM), 256>>>(h2p, HH, W3, DD, b3,
                                              nullptr, nullptr, nullptr,
                                              projp, 2 * DD, out + 1, HH, 1);
    sgemm_ep<<<dim3(DD / BN, NN / BM), 256>>>(h2p + (size_t)NN * HH, HH, W3, DD, b3,
                                              nullptr, nullptr, nullptr,
                                              projp + DD, 2 * DD, out + 1 + DD, HH, 1);

    // row norms
    norm_kernel<<<NN / 8, 256>>>();

    // fused similarity + all reductions (never materializes m)
    sim_kernel<<<dim3(NN / 128, NN / 128), 256>>>(pos, bat);

    // final scalar
    finalize_kernel<<<1, 512>>>(out);
}

// round 7
// speedup vs baseline: 1.3676x; 1.3676x over previous
#include <cuda_runtime.h>
#include <cuda_bf16.h>
#include <math.h>
#include <stdint.h>

// Problem constants
#define NN    8192
#define HH    512
#define DD    256
#define GG    64
#define M2    16384
#define EPS_G 1e-6f
#define EPS_L 1e-5f

// ---------------- scratch (static device allocations; no cudaMalloc) ----------------
__device__ float g_h1[M2 * HH];          // 32 MB
__device__ float g_h2[M2 * HH];          // 32 MB
__device__ float g_proj[NN * (2 * DD)];  // 16 MB
__device__ __nv_bfloat16 g_Ahi[NN * DD]; // normalized * 2/tau, hi part
__device__ __nv_bfloat16 g_Alo[NN * DD];
__device__ __nv_bfloat16 g_Bhi[NN * DD]; // normalized, hi part
__device__ __nv_bfloat16 g_Blo[NN * DD];
__device__ float g_rowsum[NN];
__device__ float g_colsum[NN];
__device__ float g_rowdot[NN];
__device__ float g_coldot[NN];
__device__ float g_bsim[GG * GG];
__device__ float g_psg[GG];

// ---------------- portable tensor-core helpers (sm_80+ baseline ISA) ----------------
__device__ __forceinline__ uint32_t smem_u32(const void* p) {
    uint32_t a;
    asm("{ .reg .u64 t; cvta.to.shared.u64 t, %1; cvt.u32.u64 %0, t; }" : "=r"(a) : "l"(p));
    return a;
}
__device__ __forceinline__ void ldm_x4(uint32_t* r, uint32_t a) {
    asm volatile("ldmatrix.sync.aligned.m8n8.x4.shared.b16 {%0,%1,%2,%3}, [%4];"
                 : "=r"(r[0]), "=r"(r[1]), "=r"(r[2]), "=r"(r[3]) : "r"(a));
}
__device__ __forceinline__ void ldm_x2(uint32_t* r, uint32_t a) {
    asm volatile("ldmatrix.sync.aligned.m8n8.x2.shared.b16 {%0,%1}, [%2];"
                 : "=r"(r[0]), "=r"(r[1]) : "r"(a));
}
__device__ __forceinline__ void mma_bf16(float* c, const uint32_t* a, const uint32_t* b) {
    asm volatile("mma.sync.aligned.m16n8k16.row.col.f32.bf16.bf16.f32 "
                 "{%0,%1,%2,%3}, {%4,%5,%6,%7}, {%8,%9}, {%0,%1,%2,%3};"
                 : "+f"(c[0]), "+f"(c[1]), "+f"(c[2]), "+f"(c[3])
                 : "r"(a[0]), "r"(a[1]), "r"(a[2]), "r"(a[3]), "r"(b[0]), "r"(b[1]));
}

// ---------------- zero accumulators ----------------
__global__ void zero_kernel() {
    int t = blockIdx.x * blockDim.x + threadIdx.x;
    if (t < NN) {
        g_rowsum[t] = 0.f; g_colsum[t] = 0.f;
        g_rowdot[t] = 0.f; g_coldot[t] = 0.f;
    }
}

// ---------------- generic 128x128x(8x8) SGEMM with fused epilogue (proven path) ------
#define BM 128
#define BN 128
#define BKC 16

__global__ __launch_bounds__(256) void sgemm_ep(
    const float* __restrict__ A, int lda,
    const float* __restrict__ W, int ldw,
    const float* __restrict__ bias,
    const float* __restrict__ aP, const float* __restrict__ gP, const float* __restrict__ beP,
    float* __restrict__ C, int ldc,
    float* __restrict__ C2,
    int K, int mode)
{
    __shared__ float As[BKC][BM + 4];
    __shared__ float Bs[BKC][BN + 4];
    int tid = threadIdx.x;
    int tx = tid & 15, ty = tid >> 4;
    int row0 = blockIdx.y * BM, col0 = blockIdx.x * BN;

    float acc[8][8];
#pragma unroll
    for (int i = 0; i < 8; i++)
#pragma unroll
        for (int j = 0; j < 8; j++) acc[i][j] = 0.f;

    for (int k0 = 0; k0 < K; k0 += BKC) {
#pragma unroll
        for (int l = 0; l < 2; l++) {
            int e = tid * 2 + l;
            int ar = e >> 2;
            int akq = e & 3;
            float4 v = *reinterpret_cast<const float4*>(
                &A[(size_t)(row0 + ar) * lda + k0 + akq * 4]);
            As[akq * 4 + 0][ar] = v.x;
            As[akq * 4 + 1][ar] = v.y;
            As[akq * 4 + 2][ar] = v.z;
            As[akq * 4 + 3][ar] = v.w;
        }
#pragma unroll
        for (int l = 0; l < 2; l++) {
            int e = tid * 2 + l;
            int bk = e >> 5;
            int bc = e & 31;
            *reinterpret_cast<float4*>(&Bs[bk][bc * 4]) =
                *reinterpret_cast<const float4*>(
                    &W[(size_t)(k0 + bk) * ldw + col0 + bc * 4]);
        }
        __syncthreads();
#pragma unroll
        for (int kk = 0; kk < BKC; kk++) {
            float ra[8], rb[8];
            float4 a0 = *reinterpret_cast<const float4*>(&As[kk][ty * 8]);
            float4 a1 = *reinterpret_cast<const float4*>(&As[kk][ty * 8 + 4]);
            float4 b0 = *reinterpret_cast<const float4*>(&Bs[kk][tx * 8]);
            float4 b1 = *reinterpret_cast<const float4*>(&Bs[kk][tx * 8 + 4]);
            ra[0] = a0.x; ra[1] = a0.y; ra[2] = a0.z; ra[3] = a0.w;
            ra[4] = a1.x; ra[5] = a1.y; ra[6] = a1.z; ra[7] = a1.w;
            rb[0] = b0.x; rb[1] = b0.y; rb[2] = b0.z; rb[3] = b0.w;
            rb[4] = b1.x; rb[5] = b1.y; rb[6] = b1.z; rb[7] = b1.w;
#pragma unroll
            for (int i = 0; i < 8; i++)
#pragma unroll
                for (int j = 0; j < 8; j++)
                    acc[i][j] = fmaf(ra[i], rb[j], acc[i][j]);
        }
        __syncthreads();
    }

    float a0 = (mode == 0) ? aP[0] : 0.f;
#pragma unroll
    for (int j = 0; j < 8; j++) {
        int c = col0 + tx * 8 + j;
        float bi = bias[c];
        float gg = (mode == 0) ? gP[c] : 0.f;
        float bb = (mode == 0) ? beP[c] : 0.f;
#pragma unroll
        for (int i = 0; i < 8; i++) {
            float v = acc[i][j] + bi;
            if (mode == 0) v = tanhf(a0 * v) * gg + bb;
            else           v = v / (1.f + expf(-v));
            size_t idx = (size_t)(row0 + ty * 8 + i) * ldc + c;
            C[idx] = v;
            if (C2) C2[idx] = v;
        }
    }
}

// ---------------- per-row norm + bf16 hi/lo split (2/tau folded into A) ----------------
__global__ void norm_split_kernel() {
    int warp = (blockIdx.x * blockDim.x + threadIdx.x) >> 5;
    int lane = threadIdx.x & 31;
    if (warp >= NN) return;
    const float* pa = g_proj + (size_t)warp * 512;
    float sa = 0.f, sb = 0.f;
#pragma unroll
    for (int k = lane; k < 256; k += 32) {
        float v = pa[k];        sa += v * v;
        float w = pa[256 + k];  sb += w * w;
    }
#pragma unroll
    for (int o = 16; o; o >>= 1) {
        sa += __shfl_xor_sync(0xffffffffu, sa, o);
        sb += __shfl_xor_sync(0xffffffffu, sb, o);
    }
    float ia = 2.0f * rsqrtf(sa);   // 1/tau folded into A side
    float ib = rsqrtf(sb);
#pragma unroll
    for (int k = lane; k < 256; k += 32) {
        float va = pa[k] * ia;
        __nv_bfloat16 hi = __float2bfloat16(va);
        __nv_bfloat16 lo = __float2bfloat16(va - __bfloat162float(hi));
        g_Ahi[(size_t)warp * 256 + k] = hi;
        g_Alo[(size_t)warp * 256 + k] = lo;
        float vb = pa[256 + k] * ib;
        __nv_bfloat16 hib = __float2bfloat16(vb);
        __nv_bfloat16 lob = __float2bfloat16(vb - __bfloat162float(hib));
        g_Bhi[(size_t)warp * 256 + k] = hib;
        g_Blo[(size_t)warp * 256 + k] = lob;
    }
}

// ---------------- mma.sync bf16x3 similarity tile + fused reductions ----------------
// SMEM: [0,65536) 4x16KB staging tiles (Ahi,Alo,Bhi,Blo) -- live during MMA
//       [0,66048) m-tile 128x129 fp32 -- aliases tiles post-MMA
//       [66048..] s_rs/s_rd/s_cs/s_cd, s_ts, s_psg
#define SM_A_HI 0
#define SM_A_LO 16384
#define SM_B_HI 32768
#define SM_B_LO 49152
#define SM_RS   66048
#define SM_RD   66560
#define SM_CS   67072
#define SM_CD   67584
#define SM_TS   68096
#define SM_PSG  68100
#define SIM_SMEM_TOTAL 68352

__global__ __launch_bounds__(256, 1) void sim_mma(const float* __restrict__ pos) {
    extern __shared__ char smem[];
    uint32_t sb = smem_u32(smem);
    int tid = threadIdx.x;
    int w = tid >> 5, lane = tid & 31;
    int wm = w >> 2, wn = w & 3;          // 2x4 warp grid: 64x32 warp tile
    int i0 = blockIdx.y * 128, j0 = blockIdx.x * 128;

    float* s_rs = (float*)(smem + SM_RS);
    float* s_rd = (float*)(smem + SM_RD);
    float* s_cs = (float*)(smem + SM_CS);
    float* s_cd = (float*)(smem + SM_CD);
    float* smf  = (float*)smem;           // m-tile, post-mainloop

    if (tid == 0) { *(float*)(smem + SM_TS) = 0.f; *(float*)(smem + SM_PSG) = 0.f; }
    if (tid < 128) { s_rs[tid] = 0.f; s_rd[tid] = 0.f; s_cs[tid] = 0.f; s_cd[tid] = 0.f; }

    float c[4][4][4];
#pragma unroll
    for (int mi = 0; mi < 4; mi++)
#pragma unroll
        for (int ni = 0; ni < 4; ni++)
#pragma unroll
            for (int q = 0; q < 4; q++) c[mi][ni][q] = 0.f;

    // staging indices: thread -> (row, 64B half-row)
    int srow = tid >> 1, sseg = tid & 1;
    size_t aidx0 = (size_t)(i0 + srow) * 256 + sseg * 32;
    size_t bidx0 = (size_t)(j0 + srow) * 256 + sseg * 32;

    // ldmatrix per-lane address components
    int rA = lane & 15;                    // 16 rows of the A fragment
    int cbA = (lane >> 4) * 16;            // k-byte half 0 / 16
    int rB = lane & 7;
    int cbB = ((lane >> 3) & 1) * 16;

    for (int kc = 0; kc < 4; kc++) {       // K chunks of 64
        size_t aidx = aidx0 + kc * 64;
        size_t bidx = bidx0 + kc * 64;
#pragma unroll
        for (int q = 0; q < 4; q++) {
            uint32_t off = (uint32_t)(srow * 128 + sseg * 64 + q * 16);
            uint32_t sw = off ^ ((off >> 3) & 0x70);
            *(uint4*)(smem + SM_A_HI + sw) = *(const uint4*)(g_Ahi + aidx + q * 8);
            *(uint4*)(smem + SM_A_LO + sw) = *(const uint4*)(g_Alo + aidx + q * 8);
            *(uint4*)(smem + SM_B_HI + sw) = *(const uint4*)(g_Bhi + bidx + q * 8);
            *(uint4*)(smem + SM_B_LO + sw) = *(const uint4*)(g_Blo + bidx + q * 8);
        }
        __syncthreads();

#pragma unroll
        for (int ks = 0; ks < 4; ks++) {   // k16 steps within chunk
            // B fragments for this k-step (16 regs live)
            uint32_t bhi[4][2], blo[4][2];
#pragma unroll
            for (int ni = 0; ni < 4; ni++) {
                uint32_t off = (uint32_t)((wn * 32 + ni * 8 + rB) * 128 + ks * 32 + cbB);
                uint32_t sw = off ^ ((off >> 3) & 0x70);
                ldm_x2(bhi[ni], sb + SM_B_HI + sw);
                ldm_x2(blo[ni], sb + SM_B_LO + sw);
            }
            // A fragments loaded per mi (8 regs live at a time)
#pragma unroll
            for (int mi = 0; mi < 4; mi++) {
                uint32_t ahi[4], alo[4];
                uint32_t off = (uint32_t)((wm * 64 + mi * 16 + rA) * 128 + ks * 32 + cbA);
                uint32_t sw = off ^ ((off >> 3) & 0x70);
                ldm_x4(ahi, sb + SM_A_HI + sw);
                ldm_x4(alo, sb + SM_A_LO + sw);
#pragma unroll
                for (int ni = 0; ni < 4; ni++) {
                    mma_bf16(c[mi][ni], ahi, bhi[ni]);
                    mma_bf16(c[mi][ni], ahi, blo[ni]);
                    mma_bf16(c[mi][ni], alo, bhi[ni]);
                }
            }
        }
        __syncthreads();
    }

    // ---- epilogue: exp, row reductions + pos row-pass, stage m-tile to smem ----
    float tsl = 0.f;
#pragma unroll
    for (int mi = 0; mi < 4; mi++) {
#pragma unroll
        for (int h = 0; h < 2; h++) {
            int row_local = wm * 64 + mi * 16 + h * 8 + (lane >> 2);
            int gi = i0 + row_local;
            float rsum = 0.f, rdot = 0.f;
#pragma unroll
            for (int ni = 0; ni < 4; ni++) {
                int col_local = wn * 32 + ni * 8 + (lane & 3) * 2;
                float e0 = expf(c[mi][ni][2 * h + 0]);
                float e1 = expf(c[mi][ni][2 * h + 1]);
                smf[(size_t)row_local * 129 + col_local]     = e0;
                smf[(size_t)row_local * 129 + col_local + 1] = e1;
                const float2 p = *(const float2*)(pos + (size_t)gi * NN + j0 + col_local);
                rsum += e0 + e1;
                rdot += e0 * p.x + e1 * p.y;
            }
            atomicAdd(&s_rs[row_local], rsum);
            atomicAdd(&s_rd[row_local], rdot);
            tsl += rsum;
        }
    }
#pragma unroll
    for (int o = 16; o; o >>= 1) tsl += __shfl_xor_sync(0xffffffffu, tsl, o);
    if (lane == 0) atomicAdd((float*)(smem + SM_TS), tsl);
    __syncthreads();   // m-tile complete

    // ---- column reductions from smem m-tile (pos transposed pass) ----
    {
        int cc = tid & 127, ih = tid >> 7;
        float cs = 0.f, cd = 0.f;
        const float4* pc = (const float4*)(pos + (size_t)(j0 + cc) * NN + i0 + ih * 64);
#pragma unroll
        for (int t = 0; t < 16; t++) {
            float4 p = pc[t];
            int rb2 = ih * 64 + t * 4;
            float m0 = smf[(size_t)(rb2 + 0) * 129 + cc];
            float m1 = smf[(size_t)(rb2 + 1) * 129 + cc];
            float m2 = smf[(size_t)(rb2 + 2) * 129 + cc];
            float m3 = smf[(size_t)(rb2 + 3) * 129 + cc];
            cs += m0 + m1 + m2 + m3;
            cd += m0 * p.x + m1 * p.y + m2 * p.z + m3 * p.w;
        }
        atomicAdd(&s_cs[cc], cs);
        atomicAdd(&s_cd[cc], cd);
    }
    if (i0 == j0 && tid < 128)
        atomicAdd((float*)(smem + SM_PSG), smf[(size_t)tid * 129 + tid]);
    __syncthreads();

    if (tid < 128) {
        atomicAdd(&g_rowsum[i0 + tid], s_rs[tid]);
        atomicAdd(&g_rowdot[i0 + tid], s_rd[tid]);
        atomicAdd(&g_colsum[j0 + tid], s_cs[tid]);
        atomicAdd(&g_coldot[j0 + tid], s_cd[tid]);
    }
    if (tid == 0) {
        // groups are 128-aligned: exactly one tile per (gi,gj) pair -> plain stores
        g_bsim[(i0 >> 7) * GG + (j0 >> 7)] = *(float*)(smem + SM_TS);
        if (i0 == j0) g_psg[i0 >> 7] = *(float*)(smem + SM_PSG);
    }
}

// ---------------- final scalar loss ----------------
__global__ void finalize_kernel(float* __restrict__ out) {
    __shared__ float red[512];
    int t = threadIdx.x;

    float la = 0.f, lb = 0.f;
    for (int i = t; i < NN; i += 512) {
        la += logf(g_rowdot[i] / (g_rowsum[i] + EPS_G));
        lb += logf(g_coldot[i] / (g_colsum[i] + EPS_G));
    }
    red[t] = la; __syncthreads();
    for (int s = 256; s >= 1; s >>= 1) { if (t < s) red[t] += red[t + s]; __syncthreads(); }
    float suma = red[0]; __syncthreads();
    red[t] = lb; __syncthreads();
    for (int s = 256; s >= 1; s >>= 1) { if (t < s) red[t] += red[t + s]; __syncthreads(); }
    float sumb = red[0]; __syncthreads();

    float t0 = 0.f, t1 = 0.f, tin = 0.f;
    if (t < GG) {
        float graph = g_bsim[t * GG + t];
        float n0 = 0.f, n1 = 0.f;
        for (int a = 0; a < GG; a++) { n0 += g_bsim[a * GG + t]; n1 += g_bsim[t * GG + a]; }
        n0 -= graph; n1 -= graph;
        float psg = g_psg[t];
        t0  = logf(psg / (n0 + EPS_L));
        t1  = logf(psg / (n1 + EPS_L));
        tin = logf(psg / (graph - psg + EPS_L));
    }
    red[t] = t0; __syncthreads();
    for (int s = 256; s >= 1; s >>= 1) { if (t < s) red[t] += red[t + s]; __syncthreads(); }
    float s0 = red[0]; __syncthreads();
    red[t] = t1; __syncthreads();
    for (int s = 256; s >= 1; s >>= 1) { if (t < s) red[t] += red[t + s]; __syncthreads(); }
    float s1 = red[0]; __syncthreads();
    red[t] = tin; __syncthreads();
    for (int s = 256; s >= 1; s >>= 1) { if (t < s) red[t] += red[t + s]; __syncthreads(); }
    float sin_ = red[0]; __syncthreads();

    if (t == 0) {
        float lori_a = -suma / (float)NN;
        float lori_b = -sumb / (float)NN;
        float global_loss = 0.5f * lori_a + 0.5f * lori_b;
        float loss0 = s0 / (float)GG;
        float loss1 = s1 / (float)GG;
        float inter = 0.5f * (loss0 + loss1);
        float inner = -(sin_ / (float)GG);
        out[0] = global_loss + inter + inner;
    }
}

// ---------------- launcher ----------------
extern "C" void kernel_launch(void* const* d_in, const int* in_sizes, int n_in,
                              void* d_out, int out_size) {
    const float* za  = (const float*)d_in[0];
    const float* zb  = (const float*)d_in[1];
    const float* pos = (const float*)d_in[2];
    const float* W1  = (const float*)d_in[4];
    const float* b1  = (const float*)d_in[5];
    const float* a1  = (const float*)d_in[6];
    const float* g1  = (const float*)d_in[7];
    const float* be1 = (const float*)d_in[8];
    const float* W2  = (const float*)d_in[9];
    const float* b2  = (const float*)d_in[10];
    const float* a2  = (const float*)d_in[11];
    const float* g2  = (const float*)d_in[12];
    const float* be2 = (const float*)d_in[13];
    const float* W3  = (const float*)d_in[14];
    const float* b3  = (const float*)d_in[15];
    float* out = (float*)d_out;

    float *h1p, *h2p, *projp;
    cudaGetSymbolAddress((void**)&h1p,   g_h1);
    cudaGetSymbolAddress((void**)&h2p,   g_h2);
    cudaGetSymbolAddress((void**)&projp, g_proj);

    cudaFuncSetAttribute(sim_mma, cudaFuncAttributeMaxDynamicSharedMemorySize,
                         SIM_SMEM_TOTAL);

    zero_kernel<<<32, 256>>>();

    // MLP (fp32 SIMT path, proven)
    sgemm_ep<<<dim3(HH / BN, NN / BM), 256>>>(za, HH, W1, HH, b1, a1, g1, be1,
                                              h1p, HH, nullptr, HH, 0);
    sgemm_ep<<<dim3(HH / BN, NN / BM), 256>>>(zb, HH, W1, HH, b1, a1, g1, be1,
                                              h1p + (size_t)NN * HH, HH, nullptr, HH, 0);
    sgemm_ep<<<dim3(HH / BN, M2 / BM), 256>>>(h1p, HH, W2, HH, b2, a2, g2, be2,
                                              h2p, HH, nullptr, HH, 0);
    sgemm_ep<<<dim3(DD / BN, NN / BM), 256>>>(h2p, HH, W3, DD, b3,
                                              nullptr, nullptr, nullptr,
                                              projp, 2 * DD, out + 1, HH, 1);
    sgemm_ep<<<dim3(DD / BN, NN / BM), 256>>>(h2p + (size_t)NN * HH, HH, W3, DD, b3,
                                              nullptr, nullptr, nullptr,
                                              projp + DD, 2 * DD, out + 1 + DD, HH, 1);

    // normalize + bf16 hi/lo split
    norm_split_kernel<<<NN / 8, 256>>>();

    // tensor-core similarity + fused reductions (mma.sync bf16x3)
    sim_mma<<<dim3(NN / 128, NN / 128), 256, SIM_SMEM_TOTAL>>>(pos);

    finalize_kernel<<<1, 512>>>(out);
}

// round 8
// speedup vs baseline: 1.8133x; 1.3260x over previous
#include <cuda_runtime.h>
#include <cuda_bf16.h>
#include <math.h>
#include <stdint.h>

// Problem constants
#define NN    8192
#define HH    512
#define DD    256
#define GG    64
#define M2    16384
#define EPS_G 1e-6f
#define EPS_L 1e-5f

// ---------------- scratch (static device allocations; no cudaMalloc) ----------------
__device__ __nv_bfloat16 g_x0h[M2 * HH], g_x0l[M2 * HH];  // layer1 input (za|zb split)
__device__ __nv_bfloat16 g_x1h[M2 * HH], g_x1l[M2 * HH];  // layer1 out / layer2 in
__device__ __nv_bfloat16 g_x2h[M2 * HH], g_x2l[M2 * HH];  // layer2 out / layer3 in
__device__ __nv_bfloat16 g_w1h[HH * HH], g_w1l[HH * HH];  // W1^T hi/lo  [N,K]
__device__ __nv_bfloat16 g_w2h[HH * HH], g_w2l[HH * HH];  // W2^T
__device__ __nv_bfloat16 g_w3h[DD * HH], g_w3l[DD * HH];  // W3^T  [256,512]
__device__ float g_proj[NN * (2 * DD)];                   // fp32 projections (interleaved)
__device__ __nv_bfloat16 g_Ahi[NN * DD];                  // normalized * 2/tau, hi
__device__ __nv_bfloat16 g_Alo[NN * DD];
__device__ __nv_bfloat16 g_Bhi[NN * DD];
__device__ __nv_bfloat16 g_Blo[NN * DD];
__device__ float g_rowsum[NN];
__device__ float g_colsum[NN];
__device__ float g_rowdot[NN];
__device__ float g_coldot[NN];
__device__ float g_bsim[GG * GG];
__device__ float g_psg[GG];

// ---------------- portable tensor-core helpers (sm_80+ baseline ISA) ----------------
__device__ __forceinline__ uint32_t smem_u32(const void* p) {
    uint32_t a;
    asm("{ .reg .u64 t; cvta.to.shared.u64 t, %1; cvt.u32.u64 %0, t; }" : "=r"(a) : "l"(p));
    return a;
}
__device__ __forceinline__ void ldm_x4(uint32_t* r, uint32_t a) {
    asm volatile("ldmatrix.sync.aligned.m8n8.x4.shared.b16 {%0,%1,%2,%3}, [%4];"
                 : "=r"(r[0]), "=r"(r[1]), "=r"(r[2]), "=r"(r[3]) : "r"(a));
}
__device__ __forceinline__ void ldm_x2(uint32_t* r, uint32_t a) {
    asm volatile("ldmatrix.sync.aligned.m8n8.x2.shared.b16 {%0,%1}, [%2];"
                 : "=r"(r[0]), "=r"(r[1]) : "r"(a));
}
__device__ __forceinline__ void mma_bf16(float* c, const uint32_t* a, const uint32_t* b) {
    asm volatile("mma.sync.aligned.m16n8k16.row.col.f32.bf16.bf16.f32 "
                 "{%0,%1,%2,%3}, {%4,%5,%6,%7}, {%8,%9}, {%0,%1,%2,%3};"
                 : "+f"(c[0]), "+f"(c[1]), "+f"(c[2]), "+f"(c[3])
                 : "r"(a[0]), "r"(a[1]), "r"(a[2]), "r"(a[3]), "r"(b[0]), "r"(b[1]));
}
__device__ __forceinline__ void split_bf16(float v, __nv_bfloat16& hi, __nv_bfloat16& lo) {
    hi = __float2bfloat16(v);
    lo = __float2bfloat16(v - __bfloat162float(hi));
}

// ---------------- weight transpose + split: W[K,N] fp32 -> Wt[N,K] bf16 hi/lo -------
__global__ void wsplit_kernel(const float* __restrict__ W, int Nw,
                              __nv_bfloat16* __restrict__ Th,
                              __nv_bfloat16* __restrict__ Tl, int total) {
    int t = blockIdx.x * blockDim.x + threadIdx.x;
    if (t >= total) return;
    int n = t >> 9, k = t & 511;          // K = 512 always
    float v = W[(size_t)k * Nw + n];
    __nv_bfloat16 hi, lo; split_bf16(v, hi, lo);
    Th[t] = hi; Tl[t] = lo;
}

// ---------------- input split (za|zb stacked) + accumulator zeroing -----------------
__global__ void split_in_kernel(const float* __restrict__ za, const float* __restrict__ zb) {
    int t = blockIdx.x * blockDim.x + threadIdx.x;
    if (t < NN * HH) {
        __nv_bfloat16 hi, lo;
        split_bf16(za[t], hi, lo);
        g_x0h[t] = hi; g_x0l[t] = lo;
        split_bf16(zb[t], hi, lo);
        g_x0h[t + NN * HH] = hi; g_x0l[t + NN * HH] = lo;
    }
    if (t < NN) {
        g_rowsum[t] = 0.f; g_colsum[t] = 0.f;
        g_rowdot[t] = 0.f; g_coldot[t] = 0.f;
    }
}

// ---------------- bf16x3 MLP GEMM: C[M,N] = A @ B^T (+bias) + activation -------------
// mode 0: DyT tanh(a*h)*g+be, output split to bf16 hi/lo [M,512]
// mode 1: SiLU, output fp32 to interleaved proj layout + d_out mirror
#define SM_A_HI 0
#define SM_A_LO 16384
#define SM_B_HI 32768
#define SM_B_LO 49152
#define MLP_SMEM_TOTAL 65536

__global__ __launch_bounds__(256, 1) void mlp_mma(
    const __nv_bfloat16* __restrict__ Ah, const __nv_bfloat16* __restrict__ Al,
    const __nv_bfloat16* __restrict__ Bh, const __nv_bfloat16* __restrict__ Bl,
    int K,
    const float* __restrict__ bias,
    const float* __restrict__ aP, const float* __restrict__ gP, const float* __restrict__ beP,
    __nv_bfloat16* __restrict__ Oh, __nv_bfloat16* __restrict__ Ol,
    float* __restrict__ Cp, float* __restrict__ C2,
    int mode)
{
    extern __shared__ char smem[];
    uint32_t sb = smem_u32(smem);
    int tid = threadIdx.x;
    int w = tid >> 5, lane = tid & 31;
    int wm = w >> 2, wn = w & 3;          // 2x4 warp grid, 64x32 warp tile
    int i0 = blockIdx.y * 128, j0 = blockIdx.x * 128;

    float c[4][4][4];
#pragma unroll
    for (int mi = 0; mi < 4; mi++)
#pragma unroll
        for (int ni = 0; ni < 4; ni++)
#pragma unroll
            for (int q = 0; q < 4; q++) c[mi][ni][q] = 0.f;

    int srow = tid >> 1, sseg = tid & 1;
    size_t aidx0 = (size_t)(i0 + srow) * K + sseg * 32;
    size_t bidx0 = (size_t)(j0 + srow) * K + sseg * 32;

    int rA = lane & 15;
    int cbA = (lane >> 4) * 16;
    int rB = lane & 7;
    int cbB = ((lane >> 3) & 1) * 16;

    int nkc = K >> 6;
    for (int kc = 0; kc < nkc; kc++) {
        size_t aidx = aidx0 + kc * 64;
        size_t bidx = bidx0 + kc * 64;
#pragma unroll
        for (int q = 0; q < 4; q++) {
            uint32_t off = (uint32_t)(srow * 128 + sseg * 64 + q * 16);
            uint32_t sw = off ^ ((off >> 3) & 0x70);
            *(uint4*)(smem + SM_A_HI + sw) = *(const uint4*)(Ah + aidx + q * 8);
            *(uint4*)(smem + SM_A_LO + sw) = *(const uint4*)(Al + aidx + q * 8);
            *(uint4*)(smem + SM_B_HI + sw) = *(const uint4*)(Bh + bidx + q * 8);
            *(uint4*)(smem + SM_B_LO + sw) = *(const uint4*)(Bl + bidx + q * 8);
        }
        __syncthreads();

#pragma unroll
        for (int ks = 0; ks < 4; ks++) {
            uint32_t bhi[4][2], blo[4][2];
#pragma unroll
            for (int ni = 0; ni < 4; ni++) {
                uint32_t off = (uint32_t)((wn * 32 + ni * 8 + rB) * 128 + ks * 32 + cbB);
                uint32_t sw = off ^ ((off >> 3) & 0x70);
                ldm_x2(bhi[ni], sb + SM_B_HI + sw);
                ldm_x2(blo[ni], sb + SM_B_LO + sw);
            }
#pragma unroll
            for (int mi = 0; mi < 4; mi++) {
                uint32_t ahi[4], alo[4];
                uint32_t off = (uint32_t)((wm * 64 + mi * 16 + rA) * 128 + ks * 32 + cbA);
                uint32_t sw = off ^ ((off >> 3) & 0x70);
                ldm_x4(ahi, sb + SM_A_HI + sw);
                ldm_x4(alo, sb + SM_A_LO + sw);
#pragma unroll
                for (int ni = 0; ni < 4; ni++) {
                    mma_bf16(c[mi][ni], ahi, bhi[ni]);
                    mma_bf16(c[mi][ni], ahi, blo[ni]);
                    mma_bf16(c[mi][ni], alo, bhi[ni]);
                }
            }
        }
        __syncthreads();
    }

    // ---- epilogue ----
    if (mode == 0) {
        float a0 = aP[0];
#pragma unroll
        for (int mi = 0; mi < 4; mi++) {
#pragma unroll
            for (int h = 0; h < 2; h++) {
                int m = i0 + wm * 64 + mi * 16 + h * 8 + (lane >> 2);
#pragma unroll
                for (int ni = 0; ni < 4; ni++) {
                    int c0 = j0 + wn * 32 + ni * 8 + (lane & 3) * 2;
                    float v0 = tanhf(a0 * (c[mi][ni][2 * h + 0] + bias[c0])) * gP[c0] + beP[c0];
                    float v1 = tanhf(a0 * (c[mi][ni][2 * h + 1] + bias[c0 + 1])) * gP[c0 + 1] + beP[c0 + 1];
                    __nv_bfloat16 h0, l0, h1, l1;
                    split_bf16(v0, h0, l0);
                    split_bf16(v1, h1, l1);
                    size_t idx = (size_t)m * 512 + c0;
                    *(__nv_bfloat162*)(Oh + idx) = __nv_bfloat162(h0, h1);
                    *(__nv_bfloat162*)(Ol + idx) = __nv_bfloat162(l0, l1);
                }
            }
        }
    } else {
#pragma unroll
        for (int mi = 0; mi < 4; mi++) {
#pragma unroll
            for (int h = 0; h < 2; h++) {
                int m = i0 + wm * 64 + mi * 16 + h * 8 + (lane >> 2);
                size_t base = (m < NN) ? ((size_t)m * 512) : ((size_t)(m - NN) * 512 + 256);
#pragma unroll
                for (int ni = 0; ni < 4; ni++) {
                    int c0 = j0 + wn * 32 + ni * 8 + (lane & 3) * 2;
                    float v0 = c[mi][ni][2 * h + 0] + bias[c0];
                    float v1 = c[mi][ni][2 * h + 1] + bias[c0 + 1];
                    v0 = v0 / (1.f + expf(-v0));
                    v1 = v1 / (1.f + expf(-v1));
                    size_t pr = base + c0;
                    Cp[pr] = v0; Cp[pr + 1] = v1;
                    C2[pr] = v0; C2[pr + 1] = v1;
                }
            }
        }
    }
}

// ---------------- per-row norm + bf16 hi/lo split (2/tau folded into A) ----------------
__global__ void norm_split_kernel() {
    int warp = (blockIdx.x * blockDim.x + threadIdx.x) >> 5;
    int lane = threadIdx.x & 31;
    if (warp >= NN) return;
    const float* pa = g_proj + (size_t)warp * 512;
    float sa = 0.f, sb = 0.f;
#pragma unroll
    for (int k = lane; k < 256; k += 32) {
        float v = pa[k];        sa += v * v;
        float w = pa[256 + k];  sb += w * w;
    }
#pragma unroll
    for (int o = 16; o; o >>= 1) {
        sa += __shfl_xor_sync(0xffffffffu, sa, o);
        sb += __shfl_xor_sync(0xffffffffu, sb, o);
    }
    float ia = 2.0f * rsqrtf(sa);
    float ib = rsqrtf(sb);
#pragma unroll
    for (int k = lane; k < 256; k += 32) {
        float va = pa[k] * ia;
        __nv_bfloat16 hi, lo; split_bf16(va, hi, lo);
        g_Ahi[(size_t)warp * 256 + k] = hi;
        g_Alo[(size_t)warp * 256 + k] = lo;
        float vb = pa[256 + k] * ib;
        split_bf16(vb, hi, lo);
        g_Bhi[(size_t)warp * 256 + k] = hi;
        g_Blo[(size_t)warp * 256 + k] = lo;
    }
}

// ---------------- mma.sync bf16x3 similarity tile + fused reductions (proven) --------
#define SM_RS   66048
#define SM_RD   66560
#define SM_CS   67072
#define SM_CD   67584
#define SM_TS   68096
#define SM_PSG  68100
#define SIM_SMEM_TOTAL 68352

__global__ __launch_bounds__(256, 1) void sim_mma(const float* __restrict__ pos) {
    extern __shared__ char smem[];
    uint32_t sb = smem_u32(smem);
    int tid = threadIdx.x;
    int w = tid >> 5, lane = tid & 31;
    int wm = w >> 2, wn = w & 3;
    int i0 = blockIdx.y * 128, j0 = blockIdx.x * 128;

    float* s_rs = (float*)(smem + SM_RS);
    float* s_rd = (float*)(smem + SM_RD);
    float* s_cs = (float*)(smem + SM_CS);
    float* s_cd = (float*)(smem + SM_CD);
    float* smf  = (float*)smem;

    if (tid == 0) { *(float*)(smem + SM_TS) = 0.f; *(float*)(smem + SM_PSG) = 0.f; }
    if (tid < 128) { s_rs[tid] = 0.f; s_rd[tid] = 0.f; s_cs[tid] = 0.f; s_cd[tid] = 0.f; }

    float c[4][4][4];
#pragma unroll
    for (int mi = 0; mi < 4; mi++)
#pragma unroll
        for (int ni = 0; ni < 4; ni++)
#pragma unroll
            for (int q = 0; q < 4; q++) c[mi][ni][q] = 0.f;

    int srow = tid >> 1, sseg = tid & 1;
    size_t aidx0 = (size_t)(i0 + srow) * 256 + sseg * 32;
    size_t bidx0 = (size_t)(j0 + srow) * 256 + sseg * 32;

    int rA = lane & 15;
    int cbA = (lane >> 4) * 16;
    int rB = lane & 7;
    int cbB = ((lane >> 3) & 1) * 16;

    for (int kc = 0; kc < 4; kc++) {
        size_t aidx = aidx0 + kc * 64;
        size_t bidx = bidx0 + kc * 64;
#pragma unroll
        for (int q = 0; q < 4; q++) {
            uint32_t off = (uint32_t)(srow * 128 + sseg * 64 + q * 16);
            uint32_t sw = off ^ ((off >> 3) & 0x70);
            *(uint4*)(smem + SM_A_HI + sw) = *(const uint4*)(g_Ahi + aidx + q * 8);
            *(uint4*)(smem + SM_A_LO + sw) = *(const uint4*)(g_Alo + aidx + q * 8);
            *(uint4*)(smem + SM_B_HI + sw) = *(const uint4*)(g_Bhi + bidx + q * 8);
            *(uint4*)(smem + SM_B_LO + sw) = *(const uint4*)(g_Blo + bidx + q * 8);
        }
        __syncthreads();

#pragma unroll
        for (int ks = 0; ks < 4; ks++) {
            uint32_t bhi[4][2], blo[4][2];
#pragma unroll
            for (int ni = 0; ni < 4; ni++) {
                uint32_t off = (uint32_t)((wn * 32 + ni * 8 + rB) * 128 + ks * 32 + cbB);
                uint32_t sw = off ^ ((off >> 3) & 0x70);
                ldm_x2(bhi[ni], sb + SM_B_HI + sw);
                ldm_x2(blo[ni], sb + SM_B_LO + sw);
            }
#pragma unroll
            for (int mi = 0; mi < 4; mi++) {
                uint32_t ahi[4], alo[4];
                uint32_t off = (uint32_t)((wm * 64 + mi * 16 + rA) * 128 + ks * 32 + cbA);
                uint32_t sw = off ^ ((off >> 3) & 0x70);
                ldm_x4(ahi, sb + SM_A_HI + sw);
                ldm_x4(alo, sb + SM_A_LO + sw);
#pragma unroll
                for (int ni = 0; ni < 4; ni++) {
                    mma_bf16(c[mi][ni], ahi, bhi[ni]);
                    mma_bf16(c[mi][ni], ahi, blo[ni]);
                    mma_bf16(c[mi][ni], alo, bhi[ni]);
                }
            }
        }
        __syncthreads();
    }

    float tsl = 0.f;
#pragma unroll
    for (int mi = 0; mi < 4; mi++) {
#pragma unroll
        for (int h = 0; h < 2; h++) {
            int row_local = wm * 64 + mi * 16 + h * 8 + (lane >> 2);
            int gi = i0 + row_local;
            float rsum = 0.f, rdot = 0.f;
#pragma unroll
            for (int ni = 0; ni < 4; ni++) {
                int col_local = wn * 32 + ni * 8 + (lane & 3) * 2;
                float e0 = expf(c[mi][ni][2 * h + 0]);
                float e1 = expf(c[mi][ni][2 * h + 1]);
                smf[(size_t)row_local * 129 + col_local]     = e0;
                smf[(size_t)row_local * 129 + col_local + 1] = e1;
                const float2 p = *(const float2*)(pos + (size_t)gi * NN + j0 + col_local);
                rsum += e0 + e1;
                rdot += e0 * p.x + e1 * p.y;
            }
            atomicAdd(&s_rs[row_local], rsum);
            atomicAdd(&s_rd[row_local], rdot);
            tsl += rsum;
        }
    }
#pragma unroll
    for (int o = 16; o; o >>= 1) tsl += __shfl_xor_sync(0xffffffffu, tsl, o);
    if (lane == 0) atomicAdd((float*)(smem + SM_TS), tsl);
    __syncthreads();

    {
        int cc = tid & 127, ih = tid >> 7;
        float cs = 0.f, cd = 0.f;
        const float4* pc = (const float4*)(pos + (size_t)(j0 + cc) * NN + i0 + ih * 64);
#pragma unroll
        for (int t = 0; t < 16; t++) {
            float4 p = pc[t];
            int rb2 = ih * 64 + t * 4;
            float m0 = smf[(size_t)(rb2 + 0) * 129 + cc];
            float m1 = smf[(size_t)(rb2 + 1) * 129 + cc];
            float m2 = smf[(size_t)(rb2 + 2) * 129 + cc];
            float m3 = smf[(size_t)(rb2 + 3) * 129 + cc];
            cs += m0 + m1 + m2 + m3;
            cd += m0 * p.x + m1 * p.y + m2 * p.z + m3 * p.w;
        }
        atomicAdd(&s_cs[cc], cs);
        atomicAdd(&s_cd[cc], cd);
    }
    if (i0 == j0 && tid < 128)
        atomicAdd((float*)(smem + SM_PSG), smf[(size_t)tid * 129 + tid]);
    __syncthreads();

    if (tid < 128) {
        atomicAdd(&g_rowsum[i0 + tid], s_rs[tid]);
        atomicAdd(&g_rowdot[i0 + tid], s_rd[tid]);
        atomicAdd(&g_colsum[j0 + tid], s_cs[tid]);
        atomicAdd(&g_coldot[j0 + tid], s_cd[tid]);
    }
    if (tid == 0) {
        g_bsim[(i0 >> 7) * GG + (j0 >> 7)] = *(float*)(smem + SM_TS);
        if (i0 == j0) g_psg[i0 >> 7] = *(float*)(smem + SM_PSG);
    }
}

// ---------------- final scalar loss ----------------
__global__ void finalize_kernel(float* __restrict__ out) {
    __shared__ float red[512];
    int t = threadIdx.x;

    float la = 0.f, lb = 0.f;
    for (int i = t; i < NN; i += 512) {
        la += logf(g_rowdot[i] / (g_rowsum[i] + EPS_G));
        lb += logf(g_coldot[i] / (g_colsum[i] + EPS_G));
    }
    red[t] = la; __syncthreads();
    for (int s = 256; s >= 1; s >>= 1) { if (t < s) red[t] += red[t + s]; __syncthreads(); }
    float suma = red[0]; __syncthreads();
    red[t] = lb; __syncthreads();
    for (int s = 256; s >= 1; s >>= 1) { if (t < s) red[t] += red[t + s]; __syncthreads(); }
    float sumb = red[0]; __syncthreads();

    float t0 = 0.f, t1 = 0.f, tin = 0.f;
    if (t < GG) {
        float graph = g_bsim[t * GG + t];
        float n0 = 0.f, n1 = 0.f;
        for (int a = 0; a < GG; a++) { n0 += g_bsim[a * GG + t]; n1 += g_bsim[t * GG + a]; }
        n0 -= graph; n1 -= graph;
        float psg = g_psg[t];
        t0  = logf(psg / (n0 + EPS_L));
        t1  = logf(psg / (n1 + EPS_L));
        tin = logf(psg / (graph - psg + EPS_L));
    }
    red[t] = t0; __syncthreads();
    for (int s = 256; s >= 1; s >>= 1) { if (t < s) red[t] += red[t + s]; __syncthreads(); }
    float s0 = red[0]; __syncthreads();
    red[t] = t1; __syncthreads();
    for (int s = 256; s >= 1; s >>= 1) { if (t < s) red[t] += red[t + s]; __syncthreads(); }
    float s1 = red[0]; __syncthreads();
    red[t] = tin; __syncthreads();
    for (int s = 256; s >= 1; s >>= 1) { if (t < s) red[t] += red[t + s]; __syncthreads(); }
    float sin_ = red[0]; __syncthreads();

    if (t == 0) {
        float lori_a = -suma / (float)NN;
        float lori_b = -sumb / (float)NN;
        float global_loss = 0.5f * lori_a + 0.5f * lori_b;
        float loss0 = s0 / (float)GG;
        float loss1 = s1 / (float)GG;
        float inter = 0.5f * (loss0 + loss1);
        float inner = -(sin_ / (float)GG);
        out[0] = global_loss + inter + inner;
    }
}

// ---------------- launcher ----------------
extern "C" void kernel_launch(void* const* d_in, const int* in_sizes, int n_in,
                              void* d_out, int out_size) {
    const float* za  = (const float*)d_in[0];
    const float* zb  = (const float*)d_in[1];
    const float* pos = (const float*)d_in[2];
    const float* W1  = (const float*)d_in[4];
    const float* b1  = (const float*)d_in[5];
    const float* a1  = (const float*)d_in[6];
    const float* g1  = (const float*)d_in[7];
    const float* be1 = (const float*)d_in[8];
    const float* W2  = (const float*)d_in[9];
    const float* b2  = (const float*)d_in[10];
    const float* a2  = (const float*)d_in[11];
    const float* g2  = (const float*)d_in[12];
    const float* be2 = (const float*)d_in[13];
    const float* W3  = (const float*)d_in[14];
    const float* b3  = (const float*)d_in[15];
    float* out = (float*)d_out;

    __nv_bfloat16 *x0h, *x0l, *x1h, *x1l, *x2h, *x2l;
    __nv_bfloat16 *w1h, *w1l, *w2h, *w2l, *w3h, *w3l;
    float* projp;
    cudaGetSymbolAddress((void**)&x0h, g_x0h);
    cudaGetSymbolAddress((void**)&x0l, g_x0l);
    cudaGetSymbolAddress((void**)&x1h, g_x1h);
    cudaGetSymbolAddress((void**)&x1l, g_x1l);
    cudaGetSymbolAddress((void**)&x2h, g_x2h);
    cudaGetSymbolAddress((void**)&x2l, g_x2l);
    cudaGetSymbolAddress((void**)&w1h, g_w1h);
    cudaGetSymbolAddress((void**)&w1l, g_w1l);
    cudaGetSymbolAddress((void**)&w2h, g_w2h);
    cudaGetSymbolAddress((void**)&w2l, g_w2l);
    cudaGetSymbolAddress((void**)&w3h, g_w3h);
    cudaGetSymbolAddress((void**)&w3l, g_w3l);
    cudaGetSymbolAddress((void**)&projp, g_proj);

    cudaFuncSetAttribute(mlp_mma, cudaFuncAttributeMaxDynamicSharedMemorySize,
                         MLP_SMEM_TOTAL);
    cudaFuncSetAttribute(sim_mma, cudaFuncAttributeMaxDynamicSharedMemorySize,
                         SIM_SMEM_TOTAL);

    // weight prep (transpose + hi/lo split)
    wsplit_kernel<<<(HH * HH + 255) / 256, 256>>>(W1, HH, w1h, w1l, HH * HH);
    wsplit_kernel<<<(HH * HH + 255) / 256, 256>>>(W2, HH, w2h, w2l, HH * HH);
    wsplit_kernel<<<(DD * HH + 255) / 256, 256>>>(W3, DD, w3h, w3l, DD * HH);

    // input split + accumulator zeroing
    split_in_kernel<<<(NN * HH + 255) / 256, 256>>>(za, zb);

    // MLP (bf16x3 tensor path)
    mlp_mma<<<dim3(4, 128), 256, MLP_SMEM_TOTAL>>>(x0h, x0l, w1h, w1l, HH,
                                                   b1, a1, g1, be1,
                                                   x1h, x1l, nullptr, nullptr, 0);
    mlp_mma<<<dim3(4, 128), 256, MLP_SMEM_TOTAL>>>(x1h, x1l, w2h, w2l, HH,
                                                   b2, a2, g2, be2,
                                                   x2h, x2l, nullptr, nullptr, 0);
    mlp_mma<<<dim3(2, 128), 256, MLP_SMEM_TOTAL>>>(x2h, x2l, w3h, w3l, HH,
                                                   b3, nullptr, nullptr, nullptr,
                                                   nullptr, nullptr, projp, out + 1, 1);

    // normalize + bf16 hi/lo split for sim
    norm_split_kernel<<<NN / 8, 256>>>();

    // tensor-core similarity + fused reductions
    sim_mma<<<dim3(NN / 128, NN / 128), 256, SIM_SMEM_TOTAL>>>(pos);

    finalize_kernel<<<1, 512>>>(out);
}

// round 9
// speedup vs baseline: 2.2816x; 1.2582x over previous
#include <cuda_runtime.h>
#include <cuda_bf16.h>
#include <math.h>
#include <stdint.h>

// Problem constants
#define NN    8192
#define HH    512
#define DD    256
#define GG    64
#define M2    16384
#define EPS_G 1e-6f
#define EPS_L 1e-5f

// ---------------- scratch (static device allocations; no cudaMalloc) ----------------
__device__ __nv_bfloat16 g_x0h[M2 * HH], g_x0l[M2 * HH];  // layer1 input (za|zb split)
__device__ __nv_bfloat16 g_x1h[M2 * HH], g_x1l[M2 * HH];  // layer1 out / layer2 in
__device__ __nv_bfloat16 g_x2h[M2 * HH], g_x2l[M2 * HH];  // layer2 out / layer3 in
__device__ __nv_bfloat16 g_w1h[HH * HH], g_w1l[HH * HH];  // W1^T hi/lo  [N,K]
__device__ __nv_bfloat16 g_w2h[HH * HH], g_w2l[HH * HH];  // W2^T
__device__ __nv_bfloat16 g_w3h[DD * HH], g_w3l[DD * HH];  // W3^T  [256,512]
__device__ float g_proj[NN * (2 * DD)];                   // fp32 projections (interleaved)
__device__ __nv_bfloat16 g_Ahi[NN * DD];                  // normalized * 2/tau, hi
__device__ __nv_bfloat16 g_Alo[NN * DD];
__device__ __nv_bfloat16 g_Bhi[NN * DD];
__device__ __nv_bfloat16 g_Blo[NN * DD];
__device__ float g_rowsum[NN];
__device__ float g_colsum[NN];
__device__ float g_rowdot[NN];
__device__ float g_coldot[NN];
__device__ float g_bsim[GG * GG];
__device__ float g_psg[GG];

// ---------------- portable tensor-core helpers (sm_80+ baseline ISA) ----------------
__device__ __forceinline__ uint32_t smem_u32(const void* p) {
    uint32_t a;
    asm("{ .reg .u64 t; cvta.to.shared.u64 t, %1; cvt.u32.u64 %0, t; }" : "=r"(a) : "l"(p));
    return a;
}
__device__ __forceinline__ void ldm_x4(uint32_t* r, uint32_t a) {
    asm volatile("ldmatrix.sync.aligned.m8n8.x4.shared.b16 {%0,%1,%2,%3}, [%4];"
                 : "=r"(r[0]), "=r"(r[1]), "=r"(r[2]), "=r"(r[3]) : "r"(a));
}
__device__ __forceinline__ void ldm_x2(uint32_t* r, uint32_t a) {
    asm volatile("ldmatrix.sync.aligned.m8n8.x2.shared.b16 {%0,%1}, [%2];"
                 : "=r"(r[0]), "=r"(r[1]) : "r"(a));
}
__device__ __forceinline__ void mma_bf16(float* c, const uint32_t* a, const uint32_t* b) {
    asm volatile("mma.sync.aligned.m16n8k16.row.col.f32.bf16.bf16.f32 "
                 "{%0,%1,%2,%3}, {%4,%5,%6,%7}, {%8,%9}, {%0,%1,%2,%3};"
                 : "+f"(c[0]), "+f"(c[1]), "+f"(c[2]), "+f"(c[3])
                 : "r"(a[0]), "r"(a[1]), "r"(a[2]), "r"(a[3]), "r"(b[0]), "r"(b[1]));
}
__device__ __forceinline__ void split_bf16(float v, __nv_bfloat16& hi, __nv_bfloat16& lo) {
    hi = __float2bfloat16(v);
    lo = __float2bfloat16(v - __bfloat162float(hi));
}

// ---------------- weight transpose + split: W[K,N] fp32 -> Wt[N,K] bf16 hi/lo -------
__global__ void wsplit_kernel(const float* __restrict__ W, int Nw,
                              __nv_bfloat16* __restrict__ Th,
                              __nv_bfloat16* __restrict__ Tl, int total) {
    int t = blockIdx.x * blockDim.x + threadIdx.x;
    if (t >= total) return;
    int n = t >> 9, k = t & 511;          // K = 512 always
    float v = W[(size_t)k * Nw + n];
    __nv_bfloat16 hi, lo; split_bf16(v, hi, lo);
    Th[t] = hi; Tl[t] = lo;
}

// ---------------- input split (za|zb stacked) + accumulator zeroing -----------------
__global__ void split_in_kernel(const float* __restrict__ za, const float* __restrict__ zb) {
    int t = blockIdx.x * blockDim.x + threadIdx.x;
    if (t < NN * HH) {
        __nv_bfloat16 hi, lo;
        split_bf16(za[t], hi, lo);
        g_x0h[t] = hi; g_x0l[t] = lo;
        split_bf16(zb[t], hi, lo);
        g_x0h[t + NN * HH] = hi; g_x0l[t + NN * HH] = lo;
    }
    if (t < NN) {
        g_rowsum[t] = 0.f; g_colsum[t] = 0.f;
        g_rowdot[t] = 0.f; g_coldot[t] = 0.f;
    }
}

// ---------------- bf16x3 MLP GEMM: C[M,N] = A @ B^T (+bias) + activation -------------
// mode 0: DyT tanh(a*h)*g+be, output split to bf16 hi/lo [M,512]
// mode 1: SiLU, output fp32 to interleaved proj layout + d_out mirror
#define SM_A_HI 0
#define SM_A_LO 16384
#define SM_B_HI 32768
#define SM_B_LO 49152
#define MLP_SMEM_TOTAL 65536

__global__ __launch_bounds__(256, 2) void mlp_mma(
    const __nv_bfloat16* __restrict__ Ah, const __nv_bfloat16* __restrict__ Al,
    const __nv_bfloat16* __restrict__ Bh, const __nv_bfloat16* __restrict__ Bl,
    int K,
    const float* __restrict__ bias,
    const float* __restrict__ aP, const float* __restrict__ gP, const float* __restrict__ beP,
    __nv_bfloat16* __restrict__ Oh, __nv_bfloat16* __restrict__ Ol,
    float* __restrict__ Cp, float* __restrict__ C2,
    int mode)
{
    extern __shared__ char smem[];
    uint32_t sb = smem_u32(smem);
    int tid = threadIdx.x;
    int w = tid >> 5, lane = tid & 31;
    int wm = w >> 2, wn = w & 3;          // 2x4 warp grid, 64x32 warp tile
    int i0 = blockIdx.y * 128, j0 = blockIdx.x * 128;

    float c[4][4][4];
#pragma unroll
    for (int mi = 0; mi < 4; mi++)
#pragma unroll
        for (int ni = 0; ni < 4; ni++)
#pragma unroll
            for (int q = 0; q < 4; q++) c[mi][ni][q] = 0.f;

    int srow = tid >> 1, sseg = tid & 1;
    size_t aidx0 = (size_t)(i0 + srow) * K + sseg * 32;
    size_t bidx0 = (size_t)(j0 + srow) * K + sseg * 32;

    int rA = lane & 15;
    int cbA = (lane >> 4) * 16;
    int rB = lane & 7;
    int cbB = ((lane >> 3) & 1) * 16;

    int nkc = K >> 6;
    for (int kc = 0; kc < nkc; kc++) {
        size_t aidx = aidx0 + kc * 64;
        size_t bidx = bidx0 + kc * 64;
#pragma unroll
        for (int q = 0; q < 4; q++) {
            uint32_t off = (uint32_t)(srow * 128 + sseg * 64 + q * 16);
            uint32_t sw = off ^ ((off >> 3) & 0x70);
            *(uint4*)(smem + SM_A_HI + sw) = *(const uint4*)(Ah + aidx + q * 8);
            *(uint4*)(smem + SM_A_LO + sw) = *(const uint4*)(Al + aidx + q * 8);
            *(uint4*)(smem + SM_B_HI + sw) = *(const uint4*)(Bh + bidx + q * 8);
            *(uint4*)(smem + SM_B_LO + sw) = *(const uint4*)(Bl + bidx + q * 8);
        }
        __syncthreads();

#pragma unroll
        for (int ks = 0; ks < 4; ks++) {
            uint32_t bhi[4][2], blo[4][2];
#pragma unroll
            for (int ni = 0; ni < 4; ni++) {
                uint32_t off = (uint32_t)((wn * 32 + ni * 8 + rB) * 128 + ks * 32 + cbB);
                uint32_t sw = off ^ ((off >> 3) & 0x70);
                ldm_x2(bhi[ni], sb + SM_B_HI + sw);
                ldm_x2(blo[ni], sb + SM_B_LO + sw);
            }
#pragma unroll
            for (int mi = 0; mi < 4; mi++) {
                uint32_t ahi[4], alo[4];
                uint32_t off = (uint32_t)((wm * 64 + mi * 16 + rA) * 128 + ks * 32 + cbA);
                uint32_t sw = off ^ ((off >> 3) & 0x70);
                ldm_x4(ahi, sb + SM_A_HI + sw);
                ldm_x4(alo, sb + SM_A_LO + sw);
#pragma unroll
                for (int ni = 0; ni < 4; ni++) {
                    mma_bf16(c[mi][ni], ahi, bhi[ni]);
                    mma_bf16(c[mi][ni], ahi, blo[ni]);
                    mma_bf16(c[mi][ni], alo, bhi[ni]);
                }
            }
        }
        __syncthreads();
    }

    // ---- epilogue ----
    if (mode == 0) {
        float a0 = aP[0];
#pragma unroll
        for (int mi = 0; mi < 4; mi++) {
#pragma unroll
            for (int h = 0; h < 2; h++) {
                int m = i0 + wm * 64 + mi * 16 + h * 8 + (lane >> 2);
#pragma unroll
                for (int ni = 0; ni < 4; ni++) {
                    int c0 = j0 + wn * 32 + ni * 8 + (lane & 3) * 2;
                    float v0 = tanhf(a0 * (c[mi][ni][2 * h + 0] + bias[c0])) * gP[c0] + beP[c0];
                    float v1 = tanhf(a0 * (c[mi][ni][2 * h + 1] + bias[c0 + 1])) * gP[c0 + 1] + beP[c0 + 1];
                    __nv_bfloat16 h0, l0, h1, l1;
                    split_bf16(v0, h0, l0);
                    split_bf16(v1, h1, l1);
                    size_t idx = (size_t)m * 512 + c0;
                    *(__nv_bfloat162*)(Oh + idx) = __nv_bfloat162(h0, h1);
                    *(__nv_bfloat162*)(Ol + idx) = __nv_bfloat162(l0, l1);
                }
            }
        }
    } else {
#pragma unroll
        for (int mi = 0; mi < 4; mi++) {
#pragma unroll
            for (int h = 0; h < 2; h++) {
                int m = i0 + wm * 64 + mi * 16 + h * 8 + (lane >> 2);
                size_t base = (m < NN) ? ((size_t)m * 512) : ((size_t)(m - NN) * 512 + 256);
#pragma unroll
                for (int ni = 0; ni < 4; ni++) {
                    int c0 = j0 + wn * 32 + ni * 8 + (lane & 3) * 2;
                    float v0 = c[mi][ni][2 * h + 0] + bias[c0];
                    float v1 = c[mi][ni][2 * h + 1] + bias[c0 + 1];
                    v0 = v0 / (1.f + expf(-v0));
                    v1 = v1 / (1.f + expf(-v1));
                    size_t pr = base + c0;
                    Cp[pr] = v0; Cp[pr + 1] = v1;
                    C2[pr] = v0; C2[pr + 1] = v1;
                }
            }
        }
    }
}

// ---------------- per-row norm + bf16 hi/lo split (2/tau folded into A) ----------------
__global__ void norm_split_kernel() {
    int warp = (blockIdx.x * blockDim.x + threadIdx.x) >> 5;
    int lane = threadIdx.x & 31;
    if (warp >= NN) return;
    const float* pa = g_proj + (size_t)warp * 512;
    float sa = 0.f, sb = 0.f;
#pragma unroll
    for (int k = lane; k < 256; k += 32) {
        float v = pa[k];        sa += v * v;
        float w = pa[256 + k];  sb += w * w;
    }
#pragma unroll
    for (int o = 16; o; o >>= 1) {
        sa += __shfl_xor_sync(0xffffffffu, sa, o);
        sb += __shfl_xor_sync(0xffffffffu, sb, o);
    }
    float ia = 2.0f * rsqrtf(sa);
    float ib = rsqrtf(sb);
#pragma unroll
    for (int k = lane; k < 256; k += 32) {
        float va = pa[k] * ia;
        __nv_bfloat16 hi, lo; split_bf16(va, hi, lo);
        g_Ahi[(size_t)warp * 256 + k] = hi;
        g_Alo[(size_t)warp * 256 + k] = lo;
        float vb = pa[256 + k] * ib;
        split_bf16(vb, hi, lo);
        g_Bhi[(size_t)warp * 256 + k] = hi;
        g_Blo[(size_t)warp * 256 + k] = lo;
    }
}

// ---------------- mma.sync bf16x3 similarity tile + fused reductions (proven) --------
#define SM_RS   66048
#define SM_RD   66560
#define SM_CS   67072
#define SM_CD   67584
#define SM_TS   68096
#define SM_PSG  68100
#define SIM_SMEM_TOTAL 68352

__global__ __launch_bounds__(256, 2) void sim_mma(const float* __restrict__ pos) {
    extern __shared__ char smem[];
    uint32_t sb = smem_u32(smem);
    int tid = threadIdx.x;
    int w = tid >> 5, lane = tid & 31;
    int wm = w >> 2, wn = w & 3;
    int i0 = blockIdx.y * 128, j0 = blockIdx.x * 128;

    float* s_rs = (float*)(smem + SM_RS);
    float* s_rd = (float*)(smem + SM_RD);
    float* s_cs = (float*)(smem + SM_CS);
    float* s_cd = (float*)(smem + SM_CD);
    float* smf  = (float*)smem;

    if (tid == 0) { *(float*)(smem + SM_TS) = 0.f; *(float*)(smem + SM_PSG) = 0.f; }
    if (tid < 128) { s_rs[tid] = 0.f; s_rd[tid] = 0.f; s_cs[tid] = 0.f; s_cd[tid] = 0.f; }

    float c[4][4][4];
#pragma unroll
    for (int mi = 0; mi < 4; mi++)
#pragma unroll
        for (int ni = 0; ni < 4; ni++)
#pragma unroll
            for (int q = 0; q < 4; q++) c[mi][ni][q] = 0.f;

    int srow = tid >> 1, sseg = tid & 1;
    size_t aidx0 = (size_t)(i0 + srow) * 256 + sseg * 32;
    size_t bidx0 = (size_t)(j0 + srow) * 256 + sseg * 32;

    int rA = lane & 15;
    int cbA = (lane >> 4) * 16;
    int rB = lane & 7;
    int cbB = ((lane >> 3) & 1) * 16;

    for (int kc = 0; kc < 4; kc++) {
        size_t aidx = aidx0 + kc * 64;
        size_t bidx = bidx0 + kc * 64;
#pragma unroll
        for (int q = 0; q < 4; q++) {
            uint32_t off = (uint32_t)(srow * 128 + sseg * 64 + q * 16);
            uint32_t sw = off ^ ((off >> 3) & 0x70);
            *(uint4*)(smem + SM_A_HI + sw) = *(const uint4*)(g_Ahi + aidx + q * 8);
            *(uint4*)(smem + SM_A_LO + sw) = *(const uint4*)(g_Alo + aidx + q * 8);
            *(uint4*)(smem + SM_B_HI + sw) = *(const uint4*)(g_Bhi + bidx + q * 8);
            *(uint4*)(smem + SM_B_LO + sw) = *(const uint4*)(g_Blo + bidx + q * 8);
        }
        __syncthreads();

#pragma unroll
        for (int ks = 0; ks < 4; ks++) {
            uint32_t bhi[4][2], blo[4][2];
#pragma unroll
            for (int ni = 0; ni < 4; ni++) {
                uint32_t off = (uint32_t)((wn * 32 + ni * 8 + rB) * 128 + ks * 32 + cbB);
                uint32_t sw = off ^ ((off >> 3) & 0x70);
                ldm_x2(bhi[ni], sb + SM_B_HI + sw);
                ldm_x2(blo[ni], sb + SM_B_LO + sw);
            }
#pragma unroll
            for (int mi = 0; mi < 4; mi++) {
                uint32_t ahi[4], alo[4];
                uint32_t off = (uint32_t)((wm * 64 + mi * 16 + rA) * 128 + ks * 32 + cbA);
                uint32_t sw = off ^ ((off >> 3) & 0x70);
                ldm_x4(ahi, sb + SM_A_HI + sw);
                ldm_x4(alo, sb + SM_A_LO + sw);
#pragma unroll
                for (int ni = 0; ni < 4; ni++) {
                    mma_bf16(c[mi][ni], ahi, bhi[ni]);
                    mma_bf16(c[mi][ni], ahi, blo[ni]);
                    mma_bf16(c[mi][ni], alo, bhi[ni]);
                }
            }
        }
        __syncthreads();
    }

    float tsl = 0.f;
#pragma unroll
    for (int mi = 0; mi < 4; mi++) {
#pragma unroll
        for (int h = 0; h < 2; h++) {
            int row_local = wm * 64 + mi * 16 + h * 8 + (lane >> 2);
            int gi = i0 + row_local;
            float rsum = 0.f, rdot = 0.f;
#pragma unroll
            for (int ni = 0; ni < 4; ni++) {
                int col_local = wn * 32 + ni * 8 + (lane & 3) * 2;
                float e0 = expf(c[mi][ni][2 * h + 0]);
                float e1 = expf(c[mi][ni][2 * h + 1]);
                smf[(size_t)row_local * 129 + col_local]     = e0;
                smf[(size_t)row_local * 129 + col_local + 1] = e1;
                const float2 p = *(const float2*)(pos + (size_t)gi * NN + j0 + col_local);
                rsum += e0 + e1;
                rdot += e0 * p.x + e1 * p.y;
            }
            atomicAdd(&s_rs[row_local], rsum);
            atomicAdd(&s_rd[row_local], rdot);
            tsl += rsum;
        }
    }
#pragma unroll
    for (int o = 16; o; o >>= 1) tsl += __shfl_xor_sync(0xffffffffu, tsl, o);
    if (lane == 0) atomicAdd((float*)(smem + SM_TS), tsl);
    __syncthreads();

    {
        int cc = tid & 127, ih = tid >> 7;
        float cs = 0.f, cd = 0.f;
        const float4* pc = (const float4*)(pos + (size_t)(j0 + cc) * NN + i0 + ih * 64);
#pragma unroll
        for (int t = 0; t < 16; t++) {
            float4 p = pc[t];
            int rb2 = ih * 64 + t * 4;
            float m0 = smf[(size_t)(rb2 + 0) * 129 + cc];
            float m1 = smf[(size_t)(rb2 + 1) * 129 + cc];
            float m2 = smf[(size_t)(rb2 + 2) * 129 + cc];
            float m3 = smf[(size_t)(rb2 + 3) * 129 + cc];
            cs += m0 + m1 + m2 + m3;
            cd += m0 * p.x + m1 * p.y + m2 * p.z + m3 * p.w;
        }
        atomicAdd(&s_cs[cc], cs);
        atomicAdd(&s_cd[cc], cd);
    }
    if (i0 == j0 && tid < 128)
        atomicAdd((float*)(smem + SM_PSG), smf[(size_t)tid * 129 + tid]);
    __syncthreads();

    if (tid < 128) {
        atomicAdd(&g_rowsum[i0 + tid], s_rs[tid]);
        atomicAdd(&g_rowdot[i0 + tid], s_rd[tid]);
        atomicAdd(&g_colsum[j0 + tid], s_cs[tid]);
        atomicAdd(&g_coldot[j0 + tid], s_cd[tid]);
    }
    if (tid == 0) {
        g_bsim[(i0 >> 7) * GG + (j0 >> 7)] = *(float*)(smem + SM_TS);
        if (i0 == j0) g_psg[i0 >> 7] = *(float*)(smem + SM_PSG);
    }
}

// ---------------- final scalar loss ----------------
__global__ void finalize_kernel(float* __restrict__ out) {
    __shared__ float red[512];
    int t = threadIdx.x;

    float la = 0.f, lb = 0.f;
    for (int i = t; i < NN; i += 512) {
        la += logf(g_rowdot[i] / (g_rowsum[i] + EPS_G));
        lb += logf(g_coldot[i] / (g_colsum[i] + EPS_G));
    }
    red[t] = la; __syncthreads();
    for (int s = 256; s >= 1; s >>= 1) { if (t < s) red[t] += red[t + s]; __syncthreads(); }
    float suma = red[0]; __syncthreads();
    red[t] = lb; __syncthreads();
    for (int s = 256; s >= 1; s >>= 1) { if (t < s) red[t] += red[t + s]; __syncthreads(); }
    float sumb = red[0]; __syncthreads();

    float t0 = 0.f, t1 = 0.f, tin = 0.f;
    if (t < GG) {
        float graph = g_bsim[t * GG + t];
        float n0 = 0.f, n1 = 0.f;
        for (int a = 0; a < GG; a++) { n0 += g_bsim[a * GG + t]; n1 += g_bsim[t * GG + a]; }
        n0 -= graph; n1 -= graph;
        float psg = g_psg[t];
        t0  = logf(psg / (n0 + EPS_L));
        t1  = logf(psg / (n1 + EPS_L));
        tin = logf(psg / (graph - psg + EPS_L));
    }
    red[t] = t0; __syncthreads();
    for (int s = 256; s >= 1; s >>= 1) { if (t < s) red[t] += red[t + s]; __syncthreads(); }
    float s0 = red[0]; __syncthreads();
    red[t] = t1; __syncthreads();
    for (int s = 256; s >= 1; s >>= 1) { if (t < s) red[t] += red[t + s]; __syncthreads(); }
    float s1 = red[0]; __syncthreads();
    red[t] = tin; __syncthreads();
    for (int s = 256; s >= 1; s >>= 1) { if (t < s) red[t] += red[t + s]; __syncthreads(); }
    float sin_ = red[0]; __syncthreads();

    if (t == 0) {
        float lori_a = -suma / (float)NN;
        float lori_b = -sumb / (float)NN;
        float global_loss = 0.5f * lori_a + 0.5f * lori_b;
        float loss0 = s0 / (float)GG;
        float loss1 = s1 / (float)GG;
        float inter = 0.5f * (loss0 + loss1);
        float inner = -(sin_ / (float)GG);
        out[0] = global_loss + inter + inner;
    }
}

// ---------------- launcher ----------------
extern "C" void kernel_launch(void* const* d_in, const int* in_sizes, int n_in,
                              void* d_out, int out_size) {
    const float* za  = (const float*)d_in[0];
    const float* zb  = (const float*)d_in[1];
    const float* pos = (const float*)d_in[2];
    const float* W1  = (const float*)d_in[4];
    const float* b1  = (const float*)d_in[5];
    const float* a1  = (const float*)d_in[6];
    const float* g1  = (const float*)d_in[7];
    const float* be1 = (const float*)d_in[8];
    const float* W2  = (const float*)d_in[9];
    const float* b2  = (const float*)d_in[10];
    const float* a2  = (const float*)d_in[11];
    const float* g2  = (const float*)d_in[12];
    const float* be2 = (const float*)d_in[13];
    const float* W3  = (const float*)d_in[14];
    const float* b3  = (const float*)d_in[15];
    float* out = (float*)d_out;

    __nv_bfloat16 *x0h, *x0l, *x1h, *x1l, *x2h, *x2l;
    __nv_bfloat16 *w1h, *w1l, *w2h, *w2l, *w3h, *w3l;
    float* projp;
    cudaGetSymbolAddress((void**)&x0h, g_x0h);
    cudaGetSymbolAddress((void**)&x0l, g_x0l);
    cudaGetSymbolAddress((void**)&x1h, g_x1h);
    cudaGetSymbolAddress((void**)&x1l, g_x1l);
    cudaGetSymbolAddress((void**)&x2h, g_x2h);
    cudaGetSymbolAddress((void**)&x2l, g_x2l);
    cudaGetSymbolAddress((void**)&w1h, g_w1h);
    cudaGetSymbolAddress((void**)&w1l, g_w1l);
    cudaGetSymbolAddress((void**)&w2h, g_w2h);
    cudaGetSymbolAddress((void**)&w2l, g_w2l);
    cudaGetSymbolAddress((void**)&w3h, g_w3h);
    cudaGetSymbolAddress((void**)&w3l, g_w3l);
    cudaGetSymbolAddress((void**)&projp, g_proj);

    cudaFuncSetAttribute(mlp_mma, cudaFuncAttributeMaxDynamicSharedMemorySize,
                         MLP_SMEM_TOTAL);
    cudaFuncSetAttribute(sim_mma, cudaFuncAttributeMaxDynamicSharedMemorySize,
                         SIM_SMEM_TOTAL);

    // weight prep (transpose + hi/lo split)
    wsplit_kernel<<<(HH * HH + 255) / 256, 256>>>(W1, HH, w1h, w1l, HH * HH);
    wsplit_kernel<<<(HH * HH + 255) / 256, 256>>>(W2, HH, w2h, w2l, HH * HH);
    wsplit_kernel<<<(DD * HH + 255) / 256, 256>>>(W3, DD, w3h, w3l, DD * HH);

    // input split + accumulator zeroing
    split_in_kernel<<<(NN * HH + 255) / 256, 256>>>(za, zb);

    // MLP (bf16x3 tensor path)
    mlp_mma<<<dim3(4, 128), 256, MLP_SMEM_TOTAL>>>(x0h, x0l, w1h, w1l, HH,
                                                   b1, a1, g1, be1,
                                                   x1h, x1l, nullptr, nullptr, 0);
    mlp_mma<<<dim3(4, 128), 256, MLP_SMEM_TOTAL>>>(x1h, x1l, w2h, w2l, HH,
                                                   b2, a2, g2, be2,
                                                   x2h, x2l, nullptr, nullptr, 0);
    mlp_mma<<<dim3(2, 128), 256, MLP_SMEM_TOTAL>>>(x2h, x2l, w3h, w3l, HH,
                                                   b3, nullptr, nullptr, nullptr,
                                                   nullptr, nullptr, projp, out + 1, 1);

    // normalize + bf16 hi/lo split for sim
    norm_split_kernel<<<NN / 8, 256>>>();

    // tensor-core similarity + fused reductions
    sim_mma<<<dim3(NN / 128, NN / 128), 256, SIM_SMEM_TOTAL>>>(pos);

    finalize_kernel<<<1, 512>>>(out);
}

// round 13
// speedup vs baseline: 2.7268x; 1.1951x over previous
#include <cuda_runtime.h>
#include <cuda_bf16.h>
#include <math.h>
#include <stdint.h>

// Problem constants
#define NN    8192
#define HH    512
#define DD    256
#define GG    64
#define M2    16384
#define EPS_G 1e-6f
#define EPS_L 1e-5f

// ---------------- scratch (static device allocations; no cudaMalloc) ----------------
__device__ __nv_bfloat16 g_x0h[M2 * HH], g_x0l[M2 * HH];  // layer1 input (za|zb split)
__device__ __nv_bfloat16 g_x1h[M2 * HH], g_x1l[M2 * HH];  // layer1 out / layer2 in
__device__ __nv_bfloat16 g_x2h[M2 * HH], g_x2l[M2 * HH];  // layer2 out / layer3 in
__device__ __nv_bfloat16 g_w1h[HH * HH], g_w1l[HH * HH];  // W1^T hi/lo  [N,K]
__device__ __nv_bfloat16 g_w2h[HH * HH], g_w2l[HH * HH];  // W2^T
__device__ __nv_bfloat16 g_w3h[DD * HH], g_w3l[DD * HH];  // W3^T  [256,512]
__device__ float g_proj[NN * (2 * DD)];                   // fp32 projections (interleaved)
__device__ __nv_bfloat16 g_Ahi[NN * DD];                  // normalized * 2/tau (bf16)
__device__ __nv_bfloat16 g_Bhi[NN * DD];                  // normalized (bf16)
__device__ float g_rowsum[NN];
__device__ float g_colsum[NN];
__device__ float g_rowdot[NN];
__device__ float g_coldot[NN];
__device__ float g_bsim[GG * GG];
__device__ float g_psg[GG];

// ---------------- portable tensor-core helpers (sm_80+ baseline ISA) ----------------
__device__ __forceinline__ uint32_t smem_u32(const void* p) {
    uint32_t a;
    asm("{ .reg .u64 t; cvta.to.shared.u64 t, %1; cvt.u32.u64 %0, t; }" : "=r"(a) : "l"(p));
    return a;
}
__device__ __forceinline__ void ldm_x4(uint32_t* r, uint32_t a) {
    asm volatile("ldmatrix.sync.aligned.m8n8.x4.shared.b16 {%0,%1,%2,%3}, [%4];"
                 : "=r"(r[0]), "=r"(r[1]), "=r"(r[2]), "=r"(r[3]) : "r"(a));
}
__device__ __forceinline__ void ldm_x2(uint32_t* r, uint32_t a) {
    asm volatile("ldmatrix.sync.aligned.m8n8.x2.shared.b16 {%0,%1}, [%2];"
                 : "=r"(r[0]), "=r"(r[1]) : "r"(a));
}
__device__ __forceinline__ void mma_bf16(float* c, const uint32_t* a, const uint32_t* b) {
    asm volatile("mma.sync.aligned.m16n8k16.row.col.f32.bf16.bf16.f32 "
                 "{%0,%1,%2,%3}, {%4,%5,%6,%7}, {%8,%9}, {%0,%1,%2,%3};"
                 : "+f"(c[0]), "+f"(c[1]), "+f"(c[2]), "+f"(c[3])
                 : "r"(a[0]), "r"(a[1]), "r"(a[2]), "r"(a[3]), "r"(b[0]), "r"(b[1]));
}
__device__ __forceinline__ void split_bf16(float v, __nv_bfloat16& hi, __nv_bfloat16& lo) {
    hi = __float2bfloat16(v);
    lo = __float2bfloat16(v - __bfloat162float(hi));
}

// ---------------- weight transpose + split: W[K,N] fp32 -> Wt[N,K] bf16 hi/lo -------
__global__ void wsplit_kernel(const float* __restrict__ W, int Nw,
                              __nv_bfloat16* __restrict__ Th,
                              __nv_bfloat16* __restrict__ Tl, int total) {
    int t = blockIdx.x * blockDim.x + threadIdx.x;
    if (t >= total) return;
    int n = t >> 9, k = t & 511;          // K = 512 always
    float v = W[(size_t)k * Nw + n];
    __nv_bfloat16 hi, lo; split_bf16(v, hi, lo);
    Th[t] = hi; Tl[t] = lo;
}

// ---------------- input split (za|zb stacked) + accumulator zeroing -----------------
__global__ void split_in_kernel(const float* __restrict__ za, const float* __restrict__ zb) {
    int t = blockIdx.x * blockDim.x + threadIdx.x;
    if (t < NN * HH) {
        __nv_bfloat16 hi, lo;
        split_bf16(za[t], hi, lo);
        g_x0h[t] = hi; g_x0l[t] = lo;
        split_bf16(zb[t], hi, lo);
        g_x0h[t + NN * HH] = hi; g_x0l[t + NN * HH] = lo;
    }
    if (t < NN) {
        g_rowsum[t] = 0.f; g_colsum[t] = 0.f;
        g_rowdot[t] = 0.f; g_coldot[t] = 0.f;
    }
}

// ---------------- bf16x3 MLP GEMM: C[M,N] = A @ B^T (+bias) + activation -------------
// mode 0: DyT tanh(a*h)*g+be, output split to bf16 hi/lo [M,512]
// mode 1: SiLU, output fp32 to interleaved proj layout + d_out mirror
#define SM_A_HI 0
#define SM_A_LO 16384
#define SM_B_HI 32768
#define SM_B_LO 49152
#define MLP_SMEM_TOTAL 65536

__global__ __launch_bounds__(256, 2) void mlp_mma(
    const __nv_bfloat16* __restrict__ Ah, const __nv_bfloat16* __restrict__ Al,
    const __nv_bfloat16* __restrict__ Bh, const __nv_bfloat16* __restrict__ Bl,
    int K,
    const float* __restrict__ bias,
    const float* __restrict__ aP, const float* __restrict__ gP, const float* __restrict__ beP,
    __nv_bfloat16* __restrict__ Oh, __nv_bfloat16* __restrict__ Ol,
    float* __restrict__ Cp, float* __restrict__ C2,
    int mode)
{
    extern __shared__ char smem[];
    uint32_t sb = smem_u32(smem);
    int tid = threadIdx.x;
    int w = tid >> 5, lane = tid & 31;
    int wm = w >> 2, wn = w & 3;          // 2x4 warp grid, 64x32 warp tile
    int i0 = blockIdx.y * 128, j0 = blockIdx.x * 128;

    float c[4][4][4];
#pragma unroll
    for (int mi = 0; mi < 4; mi++)
#pragma unroll
        for (int ni = 0; ni < 4; ni++)
#pragma unroll
            for (int q = 0; q < 4; q++) c[mi][ni][q] = 0.f;

    int srow = tid >> 1, sseg = tid & 1;
    size_t aidx0 = (size_t)(i0 + srow) * K + sseg * 32;
    size_t bidx0 = (size_t)(j0 + srow) * K + sseg * 32;

    int rA = lane & 15;
    int cbA = (lane >> 4) * 16;
    int rB = lane & 7;
    int cbB = ((lane >> 3) & 1) * 16;

    int nkc = K >> 6;
    for (int kc = 0; kc < nkc; kc++) {
        size_t aidx = aidx0 + kc * 64;
        size_t bidx = bidx0 + kc * 64;
#pragma unroll
        for (int q = 0; q < 4; q++) {
            uint32_t off = (uint32_t)(srow * 128 + sseg * 64 + q * 16);
            uint32_t sw = off ^ ((off >> 3) & 0x70);
            *(uint4*)(smem + SM_A_HI + sw) = *(const uint4*)(Ah + aidx + q * 8);
            *(uint4*)(smem + SM_A_LO + sw) = *(const uint4*)(Al + aidx + q * 8);
            *(uint4*)(smem + SM_B_HI + sw) = *(const uint4*)(Bh + bidx + q * 8);
            *(uint4*)(smem + SM_B_LO + sw) = *(const uint4*)(Bl + bidx + q * 8);
        }
        __syncthreads();

#pragma unroll
        for (int ks = 0; ks < 4; ks++) {
            uint32_t bhi[4][2], blo[4][2];
#pragma unroll
            for (int ni = 0; ni < 4; ni++) {
                uint32_t off = (uint32_t)((wn * 32 + ni * 8 + rB) * 128 + ks * 32 + cbB);
                uint32_t sw = off ^ ((off >> 3) & 0x70);
                ldm_x2(bhi[ni], sb + SM_B_HI + sw);
                ldm_x2(blo[ni], sb + SM_B_LO + sw);
            }
#pragma unroll
            for (int mi = 0; mi < 4; mi++) {
                uint32_t ahi[4], alo[4];
                uint32_t off = (uint32_t)((wm * 64 + mi * 16 + rA) * 128 + ks * 32 + cbA);
                uint32_t sw = off ^ ((off >> 3) & 0x70);
                ldm_x4(ahi, sb + SM_A_HI + sw);
                ldm_x4(alo, sb + SM_A_LO + sw);
#pragma unroll
                for (int ni = 0; ni < 4; ni++) {
                    mma_bf16(c[mi][ni], ahi, bhi[ni]);
                    mma_bf16(c[mi][ni], ahi, blo[ni]);
                    mma_bf16(c[mi][ni], alo, bhi[ni]);
                }
            }
        }
        __syncthreads();
    }

    // ---- epilogue ----
    if (mode == 0) {
        float a0 = aP[0];
#pragma unroll
        for (int mi = 0; mi < 4; mi++) {
#pragma unroll
            for (int h = 0; h < 2; h++) {
                int m = i0 + wm * 64 + mi * 16 + h * 8 + (lane >> 2);
#pragma unroll
                for (int ni = 0; ni < 4; ni++) {
                    int c0 = j0 + wn * 32 + ni * 8 + (lane & 3) * 2;
                    float v0 = tanhf(a0 * (c[mi][ni][2 * h + 0] + bias[c0])) * gP[c0] + beP[c0];
                    float v1 = tanhf(a0 * (c[mi][ni][2 * h + 1] + bias[c0 + 1])) * gP[c0 + 1] + beP[c0 + 1];
                    __nv_bfloat16 h0, l0, h1, l1;
                    split_bf16(v0, h0, l0);
                    split_bf16(v1, h1, l1);
                    size_t idx = (size_t)m * 512 + c0;
                    *(__nv_bfloat162*)(Oh + idx) = __nv_bfloat162(h0, h1);
                    *(__nv_bfloat162*)(Ol + idx) = __nv_bfloat162(l0, l1);
                }
            }
        }
    } else {
#pragma unroll
        for (int mi = 0; mi < 4; mi++) {
#pragma unroll
            for (int h = 0; h < 2; h++) {
                int m = i0 + wm * 64 + mi * 16 + h * 8 + (lane >> 2);
                size_t base = (m < NN) ? ((size_t)m * 512) : ((size_t)(m - NN) * 512 + 256);
#pragma unroll
                for (int ni = 0; ni < 4; ni++) {
                    int c0 = j0 + wn * 32 + ni * 8 + (lane & 3) * 2;
                    float v0 = c[mi][ni][2 * h + 0] + bias[c0];
                    float v1 = c[mi][ni][2 * h + 1] + bias[c0 + 1];
                    v0 = v0 / (1.f + expf(-v0));
                    v1 = v1 / (1.f + expf(-v1));
                    size_t pr = base + c0;
                    Cp[pr] = v0; Cp[pr + 1] = v1;
                    C2[pr] = v0; C2[pr + 1] = v1;
                }
            }
        }
    }
}

// ---------------- per-row norm + bf16 quantize (2/tau folded into A) ----------------
__global__ void norm_split_kernel() {
    int warp = (blockIdx.x * blockDim.x + threadIdx.x) >> 5;
    int lane = threadIdx.x & 31;
    if (warp >= NN) return;
    const float* pa = g_proj + (size_t)warp * 512;
    float sa = 0.f, sb = 0.f;
#pragma unroll
    for (int k = lane; k < 256; k += 32) {
        float v = pa[k];        sa += v * v;
        float w = pa[256 + k];  sb += w * w;
    }
#pragma unroll
    for (int o = 16; o; o >>= 1) {
        sa += __shfl_xor_sync(0xffffffffu, sa, o);
        sb += __shfl_xor_sync(0xffffffffu, sb, o);
    }
    float ia = 2.0f * rsqrtf(sa);
    float ib = rsqrtf(sb);
#pragma unroll
    for (int k = lane; k < 256; k += 32) {
        g_Ahi[(size_t)warp * 256 + k] = __float2bfloat16(pa[k] * ia);
        g_Bhi[(size_t)warp * 256 + k] = __float2bfloat16(pa[256 + k] * ib);
    }
}

// ---------------- mma.sync bf16 (1-term) similarity tile + fused reductions ----------
// SMEM: [0,16384)  A tile, [16384,32768) B tile  -- live during MMA
//       [0,66048)  m-tile 128x129 fp32           -- aliases tiles post-MMA
//       [66048..]  s_rs/s_rd/s_cs/s_cd, s_ts, s_psg
#define SIM_A   0
#define SIM_B   16384
#define SM_RS   66048
#define SM_RD   66560
#define SM_CS   67072
#define SM_CD   67584
#define SM_TS   68096
#define SM_PSG  68100
#define SIM_SMEM_TOTAL 68352

__global__ __launch_bounds__(256, 2) void sim_mma(const float* __restrict__ pos) {
    extern __shared__ char smem[];
    uint32_t sb = smem_u32(smem);
    int tid = threadIdx.x;
    int w = tid >> 5, lane = tid & 31;
    int wm = w >> 2, wn = w & 3;
    int i0 = blockIdx.y * 128, j0 = blockIdx.x * 128;

    float* s_rs = (float*)(smem + SM_RS);
    float* s_rd = (float*)(smem + SM_RD);
    float* s_cs = (float*)(smem + SM_CS);
    float* s_cd = (float*)(smem + SM_CD);
    float* smf  = (float*)smem;

    if (tid == 0) { *(float*)(smem + SM_TS) = 0.f; *(float*)(smem + SM_PSG) = 0.f; }
    if (tid < 128) { s_rs[tid] = 0.f; s_rd[tid] = 0.f; s_cs[tid] = 0.f; s_cd[tid] = 0.f; }

    float c[4][4][4];
#pragma unroll
    for (int mi = 0; mi < 4; mi++)
#pragma unroll
        for (int ni = 0; ni < 4; ni++)
#pragma unroll
            for (int q = 0; q < 4; q++) c[mi][ni][q] = 0.f;

    int srow = tid >> 1, sseg = tid & 1;
    size_t aidx0 = (size_t)(i0 + srow) * 256 + sseg * 32;
    size_t bidx0 = (size_t)(j0 + srow) * 256 + sseg * 32;

    int rA = lane & 15;
    int cbA = (lane >> 4) * 16;
    int rB = lane & 7;
    int cbB = ((lane >> 3) & 1) * 16;

    for (int kc = 0; kc < 4; kc++) {
        size_t aidx = aidx0 + kc * 64;
        size_t bidx = bidx0 + kc * 64;
#pragma unroll
        for (int q = 0; q < 4; q++) {
            uint32_t off = (uint32_t)(srow * 128 + sseg * 64 + q * 16);
            uint32_t sw = off ^ ((off >> 3) & 0x70);
            *(uint4*)(smem + SIM_A + sw) = *(const uint4*)(g_Ahi + aidx + q * 8);
            *(uint4*)(smem + SIM_B + sw) = *(const uint4*)(g_Bhi + bidx + q * 8);
        }
        __syncthreads();

#pragma unroll
        for (int ks = 0; ks < 4; ks++) {
            uint32_t bf[4][2];
#pragma unroll
            for (int ni = 0; ni < 4; ni++) {
                uint32_t off = (uint32_t)((wn * 32 + ni * 8 + rB) * 128 + ks * 32 + cbB);
                uint32_t sw = off ^ ((off >> 3) & 0x70);
                ldm_x2(bf[ni], sb + SIM_B + sw);
            }
#pragma unroll
            for (int mi = 0; mi < 4; mi++) {
                uint32_t af[4];
                uint32_t off = (uint32_t)((wm * 64 + mi * 16 + rA) * 128 + ks * 32 + cbA);
                uint32_t sw = off ^ ((off >> 3) & 0x70);
                ldm_x4(af, sb + SIM_A + sw);
#pragma unroll
                for (int ni = 0; ni < 4; ni++)
                    mma_bf16(c[mi][ni], af, bf[ni]);
            }
        }
        __syncthreads();
    }

    float tsl = 0.f;
#pragma unroll
    for (int mi = 0; mi < 4; mi++) {
#pragma unroll
        for (int h = 0; h < 2; h++) {
            int row_local = wm * 64 + mi * 16 + h * 8 + (lane >> 2);
            int gi = i0 + row_local;
            float rsum = 0.f, rdot = 0.f;
#pragma unroll
            for (int ni = 0; ni < 4; ni++) {
                int col_local = wn * 32 + ni * 8 + (lane & 3) * 2;
                float e0 = expf(c[mi][ni][2 * h + 0]);
                float e1 = expf(c[mi][ni][2 * h + 1]);
                smf[(size_t)row_local * 129 + col_local]     = e0;
                smf[(size_t)row_local * 129 + col_local + 1] = e1;
                const float2 p = *(const float2*)(pos + (size_t)gi * NN + j0 + col_local);
                rsum += e0 + e1;
                rdot += e0 * p.x + e1 * p.y;
            }
            atomicAdd(&s_rs[row_local], rsum);
            atomicAdd(&s_rd[row_local], rdot);
            tsl += rsum;
        }
    }
#pragma unroll
    for (int o = 16; o; o >>= 1) tsl += __shfl_xor_sync(0xffffffffu, tsl, o);
    if (lane == 0) atomicAdd((float*)(smem + SM_TS), tsl);
    __syncthreads();

    {
        int cc = tid & 127, ih = tid >> 7;
        float cs = 0.f, cd = 0.f;
        const float4* pc = (const float4*)(pos + (size_t)(j0 + cc) * NN + i0 + ih * 64);
#pragma unroll
        for (int t = 0; t < 16; t++) {
            float4 p = pc[t];
            int rb2 = ih * 64 + t * 4;
            float m0 = smf[(size_t)(rb2 + 0) * 129 + cc];
            float m1 = smf[(size_t)(rb2 + 1) * 129 + cc];
            float m2 = smf[(size_t)(rb2 + 2) * 129 + cc];
            float m3 = smf[(size_t)(rb2 + 3) * 129 + cc];
            cs += m0 + m1 + m2 + m3;
            cd += m0 * p.x + m1 * p.y + m2 * p.z + m3 * p.w;
        }
        atomicAdd(&s_cs[cc], cs);
        atomicAdd(&s_cd[cc], cd);
    }
    if (i0 == j0 && tid < 128)
        atomicAdd((float*)(smem + SM_PSG), smf[(size_t)tid * 129 + tid]);
    __syncthreads();

    if (tid < 128) {
        atomicAdd(&g_rowsum[i0 + tid], s_rs[tid]);
        atomicAdd(&g_rowdot[i0 + tid], s_rd[tid]);
        atomicAdd(&g_colsum[j0 + tid], s_cs[tid]);
        atomicAdd(&g_coldot[j0 + tid], s_cd[tid]);
    }
    if (tid == 0) {
        g_bsim[(i0 >> 7) * GG + (j0 >> 7)] = *(float*)(smem + SM_TS);
        if (i0 == j0) g_psg[i0 >> 7] = *(float*)(smem + SM_PSG);
    }
}

// ---------------- final scalar loss ----------------
__global__ void finalize_kernel(float* __restrict__ out) {
    __shared__ float red[512];
    int t = threadIdx.x;

    float la = 0.f, lb = 0.f;
    for (int i = t; i < NN; i += 512) {
        la += logf(g_rowdot[i] / (g_rowsum[i] + EPS_G));
        lb += logf(g_coldot[i] / (g_colsum[i] + EPS_G));
    }
    red[t] = la; __syncthreads();
    for (int s = 256; s >= 1; s >>= 1) { if (t < s) red[t] += red[t + s]; __syncthreads(); }
    float suma = red[0]; __syncthreads();
    red[t] = lb; __syncthreads();
    for (int s = 256; s >= 1; s >>= 1) { if (t < s) red[t] += red[t + s]; __syncthreads(); }
    float sumb = red[0]; __syncthreads();

    float t0 = 0.f, t1 = 0.f, tin = 0.f;
    if (t < GG) {
        float graph = g_bsim[t * GG + t];
        float n0 = 0.f, n1 = 0.f;
        for (int a = 0; a < GG; a++) { n0 += g_bsim[a * GG + t]; n1 += g_bsim[t * GG + a]; }
        n0 -= graph; n1 -= graph;
        float psg = g_psg[t];
        t0  = logf(psg / (n0 + EPS_L));
        t1  = logf(psg / (n1 + EPS_L));
        tin = logf(psg / (graph - psg + EPS_L));
    }
    red[t] = t0; __syncthreads();
    for (int s = 256; s >= 1; s >>= 1) { if (t < s) red[t] += red[t + s]; __syncthreads(); }
    float s0 = red[0]; __syncthreads();
    red[t] = t1; __syncthreads();
    for (int s = 256; s >= 1; s >>= 1) { if (t < s) red[t] += red[t + s]; __syncthreads(); }
    float s1 = red[0]; __syncthreads();
    red[t] = tin; __syncthreads();
    for (int s = 256; s >= 1; s >>= 1) { if (t < s) red[t] += red[t + s]; __syncthreads(); }
    float sin_ = red[0]; __syncthreads();

    if (t == 0) {
        float lori_a = -suma / (float)NN;
        float lori_b = -sumb / (float)NN;
        float global_loss = 0.5f * lori_a + 0.5f * lori_b;
        float loss0 = s0 / (float)GG;
        float loss1 = s1 / (float)GG;
        float inter = 0.5f * (loss0 + loss1);
        float inner = -(sin_ / (float)GG);
        out[0] = global_loss + inter + inner;
    }
}

// ---------------- launcher ----------------
extern "C" void kernel_launch(void* const* d_in, const int* in_sizes, int n_in,
                              void* d_out, int out_size) {
    const float* za  = (const float*)d_in[0];
    const float* zb  = (const float*)d_in[1];
    const float* pos = (const float*)d_in[2];
    const float* W1  = (const float*)d_in[4];
    const float* b1  = (const float*)d_in[5];
    const float* a1  = (const float*)d_in[6];
    const float* g1  = (const float*)d_in[7];
    const float* be1 = (const float*)d_in[8];
    const float* W2  = (const float*)d_in[9];
    const float* b2  = (const float*)d_in[10];
    const float* a2  = (const float*)d_in[11];
    const float* g2  = (const float*)d_in[12];
    const float* be2 = (const float*)d_in[13];
    const float* W3  = (const float*)d_in[14];
    const float* b3  = (const float*)d_in[15];
    float* out = (float*)d_out;

    __nv_bfloat16 *x0h, *x0l, *x1h, *x1l, *x2h, *x2l;
    __nv_bfloat16 *w1h, *w1l, *w2h, *w2l, *w3h, *w3l;
    float* projp;
    cudaGetSymbolAddress((void**)&x0h, g_x0h);
    cudaGetSymbolAddress((void**)&x0l, g_x0l);
    cudaGetSymbolAddress((void**)&x1h, g_x1h);
    cudaGetSymbolAddress((void**)&x1l, g_x1l);
    cudaGetSymbolAddress((void**)&x2h, g_x2h);
    cudaGetSymbolAddress((void**)&x2l, g_x2l);
    cudaGetSymbolAddress((void**)&w1h, g_w1h);
    cudaGetSymbolAddress((void**)&w1l, g_w1l);
    cudaGetSymbolAddress((void**)&w2h, g_w2h);
    cudaGetSymbolAddress((void**)&w2l, g_w2l);
    cudaGetSymbolAddress((void**)&w3h, g_w3h);
    cudaGetSymbolAddress((void**)&w3l, g_w3l);
    cudaGetSymbolAddress((void**)&projp, g_proj);

    cudaFuncSetAttribute(mlp_mma, cudaFuncAttributeMaxDynamicSharedMemorySize,
                         MLP_SMEM_TOTAL);
    cudaFuncSetAttribute(sim_mma, cudaFuncAttributeMaxDynamicSharedMemorySize,
                         SIM_SMEM_TOTAL);

    // weight prep (transpose + hi/lo split)
    wsplit_kernel<<<(HH * HH + 255) / 256, 256>>>(W1, HH, w1h, w1l, HH * HH);
    wsplit_kernel<<<(HH * HH + 255) / 256, 256>>>(W2, HH, w2h, w2l, HH * HH);
    wsplit_kernel<<<(DD * HH + 255) / 256, 256>>>(W3, DD, w3h, w3l, DD * HH);

    // input split + accumulator zeroing
    split_in_kernel<<<(NN * HH + 255) / 256, 256>>>(za, zb);

    // MLP (bf16x3 tensor path — projections must stay near-fp32 accurate)
    mlp_mma<<<dim3(4, 128), 256, MLP_SMEM_TOTAL>>>(x0h, x0l, w1h, w1l, HH,
                                                   b1, a1, g1, be1,
                                                   x1h, x1l, nullptr, nullptr, 0);
    mlp_mma<<<dim3(4, 128), 256, MLP_SMEM_TOTAL>>>(x1h, x1l, w2h, w2l, HH,
                                                   b2, a2, g2, be2,
                                                   x2h, x2l, nullptr, nullptr, 0);
    mlp_mma<<<dim3(2, 128), 256, MLP_SMEM_TOTAL>>>(x2h, x2l, w3h, w3l, HH,
                                                   b3, nullptr, nullptr, nullptr,
                                                   nullptr, nullptr, projp, out + 1, 1);

    // normalize + bf16 quantize for sim
    norm_split_kernel<<<NN / 8, 256>>>();

    // tensor-core similarity + fused reductions (1-term bf16; loss-side error
    // is incoherently averaged over 8192-67M terms -> ~1e-5, far under 1e-3)
    sim_mma<<<dim3(NN / 128, NN / 128), 256, SIM_SMEM_TOTAL>>>(pos);

    finalize_kernel<<<1, 512>>>(out);
}

// round 14
// speedup vs baseline: 3.0523x; 1.1194x over previous
#include <cuda_runtime.h>
#include <cuda_bf16.h>
#include <math.h>
#include <stdint.h>

// Problem constants
#define NN    8192
#define HH    512
#define DD    256
#define GG    64
#define M2    16384
#define EPS_G 1e-6f
#define EPS_L 1e-5f

// ---------------- scratch (static device allocations; no cudaMalloc) ----------------
__device__ __nv_bfloat16 g_x0h[M2 * HH], g_x0l[M2 * HH];  // layer1 input (za|zb split)
__device__ __nv_bfloat16 g_x1h[M2 * HH], g_x1l[M2 * HH];  // layer1 out / layer2 in
__device__ __nv_bfloat16 g_x2h[M2 * HH], g_x2l[M2 * HH];  // layer2 out / layer3 in
__device__ __nv_bfloat16 g_w1h[HH * HH], g_w1l[HH * HH];  // W1^T hi/lo  [N,K]
__device__ __nv_bfloat16 g_w2h[HH * HH], g_w2l[HH * HH];  // W2^T
__device__ __nv_bfloat16 g_w3h[DD * HH], g_w3l[DD * HH];  // W3^T  [256,512]
__device__ float g_proj[NN * (2 * DD)];                   // fp32 projections (interleaved)
__device__ __nv_bfloat16 g_Ahi[NN * DD];                  // normalized * 2/tau (bf16)
__device__ __nv_bfloat16 g_Bhi[NN * DD];                  // normalized (bf16)
__device__ float g_rowsum[NN];
__device__ float g_colsum[NN];
__device__ float g_rowdot[NN];
__device__ float g_coldot[NN];
__device__ float g_bsim[GG * GG];
__device__ float g_psg[GG];

// ---------------- portable tensor-core helpers (sm_80+ baseline ISA) ----------------
__device__ __forceinline__ uint32_t smem_u32(const void* p) {
    uint32_t a;
    asm("{ .reg .u64 t; cvta.to.shared.u64 t, %1; cvt.u32.u64 %0, t; }" : "=r"(a) : "l"(p));
    return a;
}
__device__ __forceinline__ void ldm_x4(uint32_t* r, uint32_t a) {
    asm volatile("ldmatrix.sync.aligned.m8n8.x4.shared.b16 {%0,%1,%2,%3}, [%4];"
                 : "=r"(r[0]), "=r"(r[1]), "=r"(r[2]), "=r"(r[3]) : "r"(a));
}
__device__ __forceinline__ void ldm_x2(uint32_t* r, uint32_t a) {
    asm volatile("ldmatrix.sync.aligned.m8n8.x2.shared.b16 {%0,%1}, [%2];"
                 : "=r"(r[0]), "=r"(r[1]) : "r"(a));
}
__device__ __forceinline__ void mma_bf16(float* c, const uint32_t* a, const uint32_t* b) {
    asm volatile("mma.sync.aligned.m16n8k16.row.col.f32.bf16.bf16.f32 "
                 "{%0,%1,%2,%3}, {%4,%5,%6,%7}, {%8,%9}, {%0,%1,%2,%3};"
                 : "+f"(c[0]), "+f"(c[1]), "+f"(c[2]), "+f"(c[3])
                 : "r"(a[0]), "r"(a[1]), "r"(a[2]), "r"(a[3]), "r"(b[0]), "r"(b[1]));
}
__device__ __forceinline__ void split_bf16(float v, __nv_bfloat16& hi, __nv_bfloat16& lo) {
    hi = __float2bfloat16(v);
    lo = __float2bfloat16(v - __bfloat162float(hi));
}
__device__ __forceinline__ void cp_async16(uint32_t saddr, const void* gptr) {
    asm volatile("cp.async.cg.shared.global [%0], [%1], 16;"
                 :: "r"(saddr), "l"(gptr) : "memory");
}
__device__ __forceinline__ void cp_commit() {
    asm volatile("cp.async.commit_group;" ::: "memory");
}
__device__ __forceinline__ void cp_wait0() {
    asm volatile("cp.async.wait_group 0;" ::: "memory");
}
__device__ __forceinline__ void cp_wait1() {
    asm volatile("cp.async.wait_group 1;" ::: "memory");
}

// ---------------- fused weight transpose + split (all 3 weights, one launch) --------
__global__ void wsplit_all(const float* __restrict__ W1, const float* __restrict__ W2,
                           const float* __restrict__ W3) {
    int t = blockIdx.x * blockDim.x + threadIdx.x;
    const float* W; __nv_bfloat16 *Th, *Tl; int Nw, e;
    if (t < HH * HH) { W = W1; Th = g_w1h; Tl = g_w1l; Nw = HH; e = t; }
    else if (t < 2 * HH * HH) { W = W2; Th = g_w2h; Tl = g_w2l; Nw = HH; e = t - HH * HH; }
    else if (t < 2 * HH * HH + DD * HH) { W = W3; Th = g_w3h; Tl = g_w3l; Nw = DD; e = t - 2 * HH * HH; }
    else return;
    int n = e >> 9, k = e & 511;          // K = 512 always
    float v = W[(size_t)k * Nw + n];
    __nv_bfloat16 hi, lo; split_bf16(v, hi, lo);
    Th[e] = hi; Tl[e] = lo;
}

// ---------------- input split (za|zb stacked) + accumulator zeroing -----------------
__global__ void split_in_kernel(const float* __restrict__ za, const float* __restrict__ zb) {
    int t = blockIdx.x * blockDim.x + threadIdx.x;
    if (t < NN * HH) {
        __nv_bfloat16 hi, lo;
        split_bf16(za[t], hi, lo);
        g_x0h[t] = hi; g_x0l[t] = lo;
        split_bf16(zb[t], hi, lo);
        g_x0h[t + NN * HH] = hi; g_x0l[t + NN * HH] = lo;
    }
    if (t < NN) {
        g_rowsum[t] = 0.f; g_colsum[t] = 0.f;
        g_rowdot[t] = 0.f; g_coldot[t] = 0.f;
    }
}

// ---------------- bf16x3 MLP GEMM (proven, unchanged) --------------------------------
#define SM_A_HI 0
#define SM_A_LO 16384
#define SM_B_HI 32768
#define SM_B_LO 49152
#define MLP_SMEM_TOTAL 65536

__global__ __launch_bounds__(256, 2) void mlp_mma(
    const __nv_bfloat16* __restrict__ Ah, const __nv_bfloat16* __restrict__ Al,
    const __nv_bfloat16* __restrict__ Bh, const __nv_bfloat16* __restrict__ Bl,
    int K,
    const float* __restrict__ bias,
    const float* __restrict__ aP, const float* __restrict__ gP, const float* __restrict__ beP,
    __nv_bfloat16* __restrict__ Oh, __nv_bfloat16* __restrict__ Ol,
    float* __restrict__ Cp, float* __restrict__ C2,
    int mode)
{
    extern __shared__ char smem[];
    uint32_t sb = smem_u32(smem);
    int tid = threadIdx.x;
    int w = tid >> 5, lane = tid & 31;
    int wm = w >> 2, wn = w & 3;          // 2x4 warp grid, 64x32 warp tile
    int i0 = blockIdx.y * 128, j0 = blockIdx.x * 128;

    float c[4][4][4];
#pragma unroll
    for (int mi = 0; mi < 4; mi++)
#pragma unroll
        for (int ni = 0; ni < 4; ni++)
#pragma unroll
            for (int q = 0; q < 4; q++) c[mi][ni][q] = 0.f;

    int srow = tid >> 1, sseg = tid & 1;
    size_t aidx0 = (size_t)(i0 + srow) * K + sseg * 32;
    size_t bidx0 = (size_t)(j0 + srow) * K + sseg * 32;

    int rA = lane & 15;
    int cbA = (lane >> 4) * 16;
    int rB = lane & 7;
    int cbB = ((lane >> 3) & 1) * 16;

    int nkc = K >> 6;
    for (int kc = 0; kc < nkc; kc++) {
        size_t aidx = aidx0 + kc * 64;
        size_t bidx = bidx0 + kc * 64;
#pragma unroll
        for (int q = 0; q < 4; q++) {
            uint32_t off = (uint32_t)(srow * 128 + sseg * 64 + q * 16);
            uint32_t sw = off ^ ((off >> 3) & 0x70);
            *(uint4*)(smem + SM_A_HI + sw) = *(const uint4*)(Ah + aidx + q * 8);
            *(uint4*)(smem + SM_A_LO + sw) = *(const uint4*)(Al + aidx + q * 8);
            *(uint4*)(smem + SM_B_HI + sw) = *(const uint4*)(Bh + bidx + q * 8);
            *(uint4*)(smem + SM_B_LO + sw) = *(const uint4*)(Bl + bidx + q * 8);
        }
        __syncthreads();

#pragma unroll
        for (int ks = 0; ks < 4; ks++) {
            uint32_t bhi[4][2], blo[4][2];
#pragma unroll
            for (int ni = 0; ni < 4; ni++) {
                uint32_t off = (uint32_t)((wn * 32 + ni * 8 + rB) * 128 + ks * 32 + cbB);
                uint32_t sw = off ^ ((off >> 3) & 0x70);
                ldm_x2(bhi[ni], sb + SM_B_HI + sw);
                ldm_x2(blo[ni], sb + SM_B_LO + sw);
            }
#pragma unroll
            for (int mi = 0; mi < 4; mi++) {
                uint32_t ahi[4], alo[4];
                uint32_t off = (uint32_t)((wm * 64 + mi * 16 + rA) * 128 + ks * 32 + cbA);
                uint32_t sw = off ^ ((off >> 3) & 0x70);
                ldm_x4(ahi, sb + SM_A_HI + sw);
                ldm_x4(alo, sb + SM_A_LO + sw);
#pragma unroll
                for (int ni = 0; ni < 4; ni++) {
                    mma_bf16(c[mi][ni], ahi, bhi[ni]);
                    mma_bf16(c[mi][ni], ahi, blo[ni]);
                    mma_bf16(c[mi][ni], alo, bhi[ni]);
                }
            }
        }
        __syncthreads();
    }

    // ---- epilogue ----
    if (mode == 0) {
        float a0 = aP[0];
#pragma unroll
        for (int mi = 0; mi < 4; mi++) {
#pragma unroll
            for (int h = 0; h < 2; h++) {
                int m = i0 + wm * 64 + mi * 16 + h * 8 + (lane >> 2);
#pragma unroll
                for (int ni = 0; ni < 4; ni++) {
                    int c0 = j0 + wn * 32 + ni * 8 + (lane & 3) * 2;
                    float v0 = tanhf(a0 * (c[mi][ni][2 * h + 0] + bias[c0])) * gP[c0] + beP[c0];
                    float v1 = tanhf(a0 * (c[mi][ni][2 * h + 1] + bias[c0 + 1])) * gP[c0 + 1] + beP[c0 + 1];
                    __nv_bfloat16 h0, l0, h1, l1;
                    split_bf16(v0, h0, l0);
                    split_bf16(v1, h1, l1);
                    size_t idx = (size_t)m * 512 + c0;
                    *(__nv_bfloat162*)(Oh + idx) = __nv_bfloat162(h0, h1);
                    *(__nv_bfloat162*)(Ol + idx) = __nv_bfloat162(l0, l1);
                }
            }
        }
    } else {
#pragma unroll
        for (int mi = 0; mi < 4; mi++) {
#pragma unroll
            for (int h = 0; h < 2; h++) {
                int m = i0 + wm * 64 + mi * 16 + h * 8 + (lane >> 2);
                size_t base = (m < NN) ? ((size_t)m * 512) : ((size_t)(m - NN) * 512 + 256);
#pragma unroll
                for (int ni = 0; ni < 4; ni++) {
                    int c0 = j0 + wn * 32 + ni * 8 + (lane & 3) * 2;
                    float v0 = c[mi][ni][2 * h + 0] + bias[c0];
                    float v1 = c[mi][ni][2 * h + 1] + bias[c0 + 1];
                    v0 = v0 / (1.f + expf(-v0));
                    v1 = v1 / (1.f + expf(-v1));
                    size_t pr = base + c0;
                    Cp[pr] = v0; Cp[pr + 1] = v1;
                    C2[pr] = v0; C2[pr + 1] = v1;
                }
            }
        }
    }
}

// ---------------- per-row norm + bf16 quantize (2/tau folded into A) ----------------
__global__ void norm_split_kernel() {
    int warp = (blockIdx.x * blockDim.x + threadIdx.x) >> 5;
    int lane = threadIdx.x & 31;
    if (warp >= NN) return;
    const float* pa = g_proj + (size_t)warp * 512;
    float sa = 0.f, sb = 0.f;
#pragma unroll
    for (int k = lane; k < 256; k += 32) {
        float v = pa[k];        sa += v * v;
        float w = pa[256 + k];  sb += w * w;
    }
#pragma unroll
    for (int o = 16; o; o >>= 1) {
        sa += __shfl_xor_sync(0xffffffffu, sa, o);
        sb += __shfl_xor_sync(0xffffffffu, sb, o);
    }
    float ia = 2.0f * rsqrtf(sa);
    float ib = rsqrtf(sb);
#pragma unroll
    for (int k = lane; k < 256; k += 32) {
        g_Ahi[(size_t)warp * 256 + k] = __float2bfloat16(pa[k] * ia);
        g_Bhi[(size_t)warp * 256 + k] = __float2bfloat16(pa[256 + k] * ib);
    }
}

// ---------------- paired-tile 1-term bf16 sim + fused reductions ---------------------
// Each CTA with by <= bx handles tile (by,bx) and, if off-diagonal, tile (bx,by):
// the two passes read the same two pos blocks -> pass 2 hits L2 (halves pos DRAM).
// SMEM: double-buffered A/B tiles: buf0 A@0 B@16K, buf1 A@32K B@48K (64 KB)
//       m-tile 128x129 fp32 [0,66048) aliases buffers post-mainloop
//       arrays at 66048+
#define SIMD_A0 0
#define SIMD_B0 16384
#define SIMD_A1 32768
#define SIMD_B1 49152
#define SM_RS   66048
#define SM_RD   66560
#define SM_CS   67072
#define SM_CD   67584
#define SM_TS   68096
#define SM_PSG  68100
#define SIM_SMEM_TOTAL 68352

__global__ __launch_bounds__(256, 2) void sim_pair(const float* __restrict__ pos) {
    int by = blockIdx.y, bx = blockIdx.x;
    if (by > bx) return;                  // upper-triangle CTAs only
    extern __shared__ char smem[];
    uint32_t sb = smem_u32(smem);
    int tid = threadIdx.x;
    int w = tid >> 5, lane = tid & 31;
    int wm = w >> 2, wn = w & 3;

    float* s_rs = (float*)(smem + SM_RS);
    float* s_rd = (float*)(smem + SM_RD);
    float* s_cs = (float*)(smem + SM_CS);
    float* s_cd = (float*)(smem + SM_CD);
    float* smf  = (float*)smem;

    int srow = tid >> 1, sseg = tid & 1;
    int rA = lane & 15;
    int cbA = (lane >> 4) * 16;
    int rB = lane & 7;
    int cbB = ((lane >> 3) & 1) * 16;
    uint32_t soff0 = (uint32_t)(srow * 128 + sseg * 64);

    int npass = (by == bx) ? 1 : 2;
    for (int pass = 0; pass < npass; pass++) {
        int I = pass ? bx : by;
        int J = pass ? by : bx;
        int i0 = I * 128, j0 = J * 128;

        if (tid == 0) { *(float*)(smem + SM_TS) = 0.f; *(float*)(smem + SM_PSG) = 0.f; }
        if (tid < 128) { s_rs[tid] = 0.f; s_rd[tid] = 0.f; s_cs[tid] = 0.f; s_cd[tid] = 0.f; }

        float c[4][4][4];
#pragma unroll
        for (int mi = 0; mi < 4; mi++)
#pragma unroll
            for (int ni = 0; ni < 4; ni++)
#pragma unroll
                for (int q = 0; q < 4; q++) c[mi][ni][q] = 0.f;

        size_t aidx0 = (size_t)(i0 + srow) * 256 + sseg * 32;
        size_t bidx0 = (size_t)(j0 + srow) * 256 + sseg * 32;

        // prologue: stage chunk 0 into buf0
#pragma unroll
        for (int q = 0; q < 4; q++) {
            uint32_t off = soff0 + q * 16;
            uint32_t sw = off ^ ((off >> 3) & 0x70);
            cp_async16(sb + SIMD_A0 + sw, g_Ahi + aidx0 + q * 8);
            cp_async16(sb + SIMD_B0 + sw, g_Bhi + bidx0 + q * 8);
        }
        cp_commit();

        for (int kc = 0; kc < 4; kc++) {
            if (kc < 3) {
                uint32_t abase = (kc & 1) ? SIMD_A0 : SIMD_A1;   // next buffer
                uint32_t bbase = (kc & 1) ? SIMD_B0 : SIMD_B1;
                size_t aidx = aidx0 + (kc + 1) * 64;
                size_t bidx = bidx0 + (kc + 1) * 64;
#pragma unroll
                for (int q = 0; q < 4; q++) {
                    uint32_t off = soff0 + q * 16;
                    uint32_t sw = off ^ ((off >> 3) & 0x70);
                    cp_async16(sb + abase + sw, g_Ahi + aidx + q * 8);
                    cp_async16(sb + bbase + sw, g_Bhi + bidx + q * 8);
                }
                cp_commit();
                cp_wait1();
            } else {
                cp_wait0();
            }
            __syncthreads();

            uint32_t aC = (kc & 1) ? SIMD_A1 : SIMD_A0;          // current buffer
            uint32_t bC = (kc & 1) ? SIMD_B1 : SIMD_B0;
#pragma unroll
            for (int ks = 0; ks < 4; ks++) {
                uint32_t bf[4][2];
#pragma unroll
                for (int ni = 0; ni < 4; ni++) {
                    uint32_t off = (uint32_t)((wn * 32 + ni * 8 + rB) * 128 + ks * 32 + cbB);
                    uint32_t sw = off ^ ((off >> 3) & 0x70);
                    ldm_x2(bf[ni], sb + bC + sw);
                }
#pragma unroll
                for (int mi = 0; mi < 4; mi++) {
                    uint32_t af[4];
                    uint32_t off = (uint32_t)((wm * 64 + mi * 16 + rA) * 128 + ks * 32 + cbA);
                    uint32_t sw = off ^ ((off >> 3) & 0x70);
                    ldm_x4(af, sb + aC + sw);
#pragma unroll
                    for (int ni = 0; ni < 4; ni++)
                        mma_bf16(c[mi][ni], af, bf[ni]);
                }
            }
            __syncthreads();
        }

        // ---- epilogue: exp, row reductions + pos row-pass, stage m-tile ----
        float tsl = 0.f;
#pragma unroll
        for (int mi = 0; mi < 4; mi++) {
#pragma unroll
            for (int h = 0; h < 2; h++) {
                int row_local = wm * 64 + mi * 16 + h * 8 + (lane >> 2);
                int gi = i0 + row_local;
                float rsum = 0.f, rdot = 0.f;
#pragma unroll
                for (int ni = 0; ni < 4; ni++) {
                    int col_local = wn * 32 + ni * 8 + (lane & 3) * 2;
                    float e0 = expf(c[mi][ni][2 * h + 0]);
                    float e1 = expf(c[mi][ni][2 * h + 1]);
                    smf[(size_t)row_local * 129 + col_local]     = e0;
                    smf[(size_t)row_local * 129 + col_local + 1] = e1;
                    const float2 p = *(const float2*)(pos + (size_t)gi * NN + j0 + col_local);
                    rsum += e0 + e1;
                    rdot += e0 * p.x + e1 * p.y;
                }
                atomicAdd(&s_rs[row_local], rsum);
                atomicAdd(&s_rd[row_local], rdot);
                tsl += rsum;
            }
        }
#pragma unroll
        for (int o = 16; o; o >>= 1) tsl += __shfl_xor_sync(0xffffffffu, tsl, o);
        if (lane == 0) atomicAdd((float*)(smem + SM_TS), tsl);
        __syncthreads();   // m-tile complete

        // column reductions (pos transposed block — L2-hot on pass 2)
        {
            int cc = tid & 127, ih = tid >> 7;
            float cs = 0.f, cd = 0.f;
            const float4* pc = (const float4*)(pos + (size_t)(j0 + cc) * NN + i0 + ih * 64);
#pragma unroll
            for (int t = 0; t < 16; t++) {
                float4 p = pc[t];
                int rb2 = ih * 64 + t * 4;
                float m0 = smf[(size_t)(rb2 + 0) * 129 + cc];
                float m1 = smf[(size_t)(rb2 + 1) * 129 + cc];
                float m2 = smf[(size_t)(rb2 + 2) * 129 + cc];
                float m3 = smf[(size_t)(rb2 + 3) * 129 + cc];
                cs += m0 + m1 + m2 + m3;
                cd += m0 * p.x + m1 * p.y + m2 * p.z + m3 * p.w;
            }
            atomicAdd(&s_cs[cc], cs);
            atomicAdd(&s_cd[cc], cd);
        }
        if (i0 == j0 && tid < 128)
            atomicAdd((float*)(smem + SM_PSG), smf[(size_t)tid * 129 + tid]);
        __syncthreads();

        if (tid < 128) {
            atomicAdd(&g_rowsum[i0 + tid], s_rs[tid]);
            atomicAdd(&g_rowdot[i0 + tid], s_rd[tid]);
            atomicAdd(&g_colsum[j0 + tid], s_cs[tid]);
            atomicAdd(&g_coldot[j0 + tid], s_cd[tid]);
        }
        if (tid == 0) {
            g_bsim[I * GG + J] = *(float*)(smem + SM_TS);   // unique (I,J) per pass
            if (I == J) g_psg[I] = *(float*)(smem + SM_PSG);
        }
        __syncthreads();   // protect smem before next pass restages
    }
}

// ---------------- final scalar loss ----------------
__global__ void finalize_kernel(float* __restrict__ out) {
    __shared__ float red[512];
    int t = threadIdx.x;

    float la = 0.f, lb = 0.f;
    for (int i = t; i < NN; i += 512) {
        la += logf(g_rowdot[i] / (g_rowsum[i] + EPS_G));
        lb += logf(g_coldot[i] / (g_colsum[i] + EPS_G));
    }
    red[t] = la; __syncthreads();
    for (int s = 256; s >= 1; s >>= 1) { if (t < s) red[t] += red[t + s]; __syncthreads(); }
    float suma = red[0]; __syncthreads();
    red[t] = lb; __syncthreads();
    for (int s = 256; s >= 1; s >>= 1) { if (t < s) red[t] += red[t + s]; __syncthreads(); }
    float sumb = red[0]; __syncthreads();

    float t0 = 0.f, t1 = 0.f, tin = 0.f;
    if (t < GG) {
        float graph = g_bsim[t * GG + t];
        float n0 = 0.f, n1 = 0.f;
        for (int a = 0; a < GG; a++) { n0 += g_bsim[a * GG + t]; n1 += g_bsim[t * GG + a]; }
        n0 -= graph; n1 -= graph;
        float psg = g_psg[t];
        t0  = logf(psg / (n0 + EPS_L));
        t1  = logf(psg / (n1 + EPS_L));
        tin = logf(psg / (graph - psg + EPS_L));
    }
    red[t] = t0; __syncthreads();
    for (int s = 256; s >= 1; s >>= 1) { if (t < s) red[t] += red[t + s]; __syncthreads(); }
    float s0 = red[0]; __syncthreads();
    red[t] = t1; __syncthreads();
    for (int s = 256; s >= 1; s >>= 1) { if (t < s) red[t] += red[t + s]; __syncthreads(); }
    float s1 = red[0]; __syncthreads();
    red[t] = tin; __syncthreads();
    for (int s = 256; s >= 1; s >>= 1) { if (t < s) red[t] += red[t + s]; __syncthreads(); }
    float sin_ = red[0]; __syncthreads();

    if (t == 0) {
        float lori_a = -suma / (float)NN;
        float lori_b = -sumb / (float)NN;
        float global_loss = 0.5f * lori_a + 0.5f * lori_b;
        float loss0 = s0 / (float)GG;
        float loss1 = s1 / (float)GG;
        float inter = 0.5f * (loss0 + loss1);
        float inner = -(sin_ / (float)GG);
        out[0] = global_loss + inter + inner;
    }
}

// ---------------- launcher ----------------
extern "C" void kernel_launch(void* const* d_in, const int* in_sizes, int n_in,
                              void* d_out, int out_size) {
    const float* za  = (const float*)d_in[0];
    const float* zb  = (const float*)d_in[1];
    const float* pos = (const float*)d_in[2];
    const float* W1  = (const float*)d_in[4];
    const float* b1  = (const float*)d_in[5];
    const float* a1  = (const float*)d_in[6];
    const float* g1  = (const float*)d_in[7];
    const float* be1 = (const float*)d_in[8];
    const float* W2  = (const float*)d_in[9];
    const float* b2  = (const float*)d_in[10];
    const float* a2  = (const float*)d_in[11];
    const float* g2  = (const float*)d_in[12];
    const float* be2 = (const float*)d_in[13];
    const float* W3  = (const float*)d_in[14];
    const float* b3  = (const float*)d_in[15];
    float* out = (float*)d_out;

    __nv_bfloat16 *x0h, *x0l, *x1h, *x1l, *x2h, *x2l;
    __nv_bfloat16 *w1h, *w1l, *w2h, *w2l, *w3h, *w3l;
    float* projp;
    cudaGetSymbolAddress((void**)&x0h, g_x0h);
    cudaGetSymbolAddress((void**)&x0l, g_x0l);
    cudaGetSymbolAddress((void**)&x1h, g_x1h);
    cudaGetSymbolAddress((void**)&x1l, g_x1l);
    cudaGetSymbolAddress((void**)&x2h, g_x2h);
    cudaGetSymbolAddress((void**)&x2l, g_x2l);
    cudaGetSymbolAddress((void**)&w1h, g_w1h);
    cudaGetSymbolAddress((void**)&w1l, g_w1l);
    cudaGetSymbolAddress((void**)&w2h, g_w2h);
    cudaGetSymbolAddress((void**)&w2l, g_w2l);
    cudaGetSymbolAddress((void**)&w3h, g_w3h);
    cudaGetSymbolAddress((void**)&w3l, g_w3l);
    cudaGetSymbolAddress((void**)&projp, g_proj);

    cudaFuncSetAttribute(mlp_mma, cudaFuncAttributeMaxDynamicSharedMemorySize,
                         MLP_SMEM_TOTAL);
    cudaFuncSetAttribute(sim_pair, cudaFuncAttributeMaxDynamicSharedMemorySize,
                         SIM_SMEM_TOTAL);

    // weight prep (single fused launch)
    wsplit_all<<<(2 * HH * HH + DD * HH + 255) / 256, 256>>>(W1, W2, W3);

    // input split + accumulator zeroing
    split_in_kernel<<<(NN * HH + 255) / 256, 256>>>(za, zb);

    // MLP (bf16x3 tensor path — projections must stay near-fp32 accurate)
    mlp_mma<<<dim3(4, 128), 256, MLP_SMEM_TOTAL>>>(x0h, x0l, w1h, w1l, HH,
                                                   b1, a1, g1, be1,
                                                   x1h, x1l, nullptr, nullptr, 0);
    mlp_mma<<<dim3(4, 128), 256, MLP_SMEM_TOTAL>>>(x1h, x1l, w2h, w2l, HH,
                                                   b2, a2, g2, be2,
                                                   x2h, x2l, nullptr, nullptr, 0);
    mlp_mma<<<dim3(2, 128), 256, MLP_SMEM_TOTAL>>>(x2h, x2l, w3h, w3l, HH,
                                                   b3, nullptr, nullptr, nullptr,
                                                   nullptr, nullptr, projp, out + 1, 1);

    // normalize + bf16 quantize for sim
    norm_split_kernel<<<NN / 8, 256>>>();

    // paired-tile tensor-core similarity + fused reductions
    sim_pair<<<dim3(GG, GG), 256, SIM_SMEM_TOTAL>>>(pos);

    finalize_kernel<<<1, 512>>>(out);
}